// round 8
// baseline (speedup 1.0000x reference)
#include <cuda_runtime.h>
#include <cstdint>

#define NN    50000
#define EE    800000
#define FIN   80
#define HH    4
#define CC    96
#define DD    384
#define NCLS  20

// ---------------- device scratch (no allocations allowed) ----------------
__device__ float g_xs[(size_t)NN * DD];
__device__ float g_xd[(size_t)NN * DD];
__device__ float g_h [(size_t)NN * DD];
__device__ float g_t1[(size_t)NN * CC];
__device__ int   g_off[NN + 1];
__device__ int   g_cnt[NN];
__device__ int   g_cur[NN];
__device__ int   g_eid[EE];
__device__ int   g_csrc[EE];

// ---------------- CSR build ----------------
// cnt starts zero (zero-init at load; re-zeroed by scan_k every call)
__global__ void hist_k(const int* __restrict__ dst, int* __restrict__ cnt) {
    int i = blockIdx.x * blockDim.x + threadIdx.x;
    if (i < EE) atomicAdd(&cnt[dst[i]], 1);
}

// warp-shuffle scan; writes exclusive offsets to off AND cur, zeroes cnt
__global__ void scan_k(int* __restrict__ cnt, int* __restrict__ off,
                       int* __restrict__ cur) {
    __shared__ int wsums[32];
    __shared__ int carry_s;
    const int t = threadIdx.x, lane = t & 31, wp = t >> 5;
    if (t == 0) carry_s = 0;
    __syncthreads();
    for (int base = 0; base < NN; base += 1024) {
        int i = base + t;
        int v = (i < NN) ? cnt[i] : 0;
        int x = v;
#pragma unroll
        for (int o = 1; o < 32; o <<= 1) {
            int y = __shfl_up_sync(0xffffffffu, x, o);
            if (lane >= o) x += y;
        }
        if (lane == 31) wsums[wp] = x;
        __syncthreads();
        if (wp == 0) {
            int ws = wsums[lane];
#pragma unroll
            for (int o = 1; o < 32; o <<= 1) {
                int y = __shfl_up_sync(0xffffffffu, ws, o);
                if (lane >= o) ws += y;
            }
            wsums[lane] = ws;
        }
        __syncthreads();
        int add = (wp > 0) ? wsums[wp - 1] : 0;
        int excl = carry_s + x + add - v;
        if (i < NN) { off[i] = excl; cur[i] = excl; cnt[i] = 0; }
        int tot = wsums[31];
        __syncthreads();
        if (t == 0) carry_s += tot;
        __syncthreads();
    }
    if (t == 0) off[NN] = carry_s;
}

__global__ void scatter_k(const int* __restrict__ dst, int* __restrict__ cur,
                          int* __restrict__ eid) {
    int i = blockIdx.x * blockDim.x + threadIdx.x;
    if (i < EE) {
        int d = dst[i];
        int p = atomicAdd(&cur[d], 1);
        eid[p] = i;
    }
}

// deterministic order within segment (sort edge ids), then gather src
__global__ void sortsrc_k(const int* __restrict__ srcArr, const int* __restrict__ off,
                          int* __restrict__ eid, int* __restrict__ csrc) {
    int v = blockIdx.x * blockDim.x + threadIdx.x;
    if (v >= NN) return;
    int s = off[v], e = off[v + 1];
    for (int i = s + 1; i < e; i++) {
        int key = eid[i];
        int j = i - 1;
        while (j >= s && eid[j] > key) { eid[j + 1] = eid[j]; j--; }
        eid[j + 1] = key;
    }
    for (int i = s; i < e; i++) csrc[i] = srcArr[eid[i]];
}

// ---------------- tf32 tensor-core GEMM core: C[M,N] = A[M,K] @ B[K,N] ----------------
// 128x128 CTA tile, 8 warps (64x32 warp tiles), BK=16, mma.m16n8k8.tf32.
// Double-buffered SMEM, one barrier/iter. Column XOR-swizzle (col ^ 8*(k>>2))
// removes the 4-way conflict on transposed A stores; B-tile rows are written
// with one STS.128 per half (conflict-free, 16B-aligned since the XOR constant
// is a multiple of 8 words). Fragment loads use matching compile-time XORs.
__device__ __forceinline__ uint32_t f2tf32(float f) {
    uint32_t r;
    asm("cvt.rna.tf32.f32 %0, %1;" : "=r"(r) : "f"(f));
    return r;
}

struct SmemGemm {
    uint32_t As[2][16][136];
    uint32_t Bs[2][16][136];
};

__device__ __forceinline__ void gemm_core(SmemGemm& sm,
                                          const float* __restrict__ A,
                                          const float* __restrict__ B,
                                          float* __restrict__ C,
                                          int M, int K, int N, int bm, int bn) {
    const int t    = threadIdx.x;
    const int lane = t & 31;
    const int w    = t >> 5;
    const int wm   = (w & 1) * 64;   // warp m offset
    const int wn   = (w >> 1) * 32;  // warp n offset
    const int g    = lane >> 2;      // 0..7
    const int tid4 = lane & 3;       // 0..3

    float acc[4][4][4];
#pragma unroll
    for (int i = 0; i < 4; i++)
#pragma unroll
        for (int j = 0; j < 4; j++)
#pragma unroll
            for (int r = 0; r < 4; r++) acc[i][j][r] = 0.f;

    // global-load mappings
    const int am  = t >> 2;          // 0..63 (+64 for second half)
    const int ak  = (t & 3) * 4;     // k quad (k = ak..ak+3, k>>2 = t&3)
    const int axr = (t & 3) * 8;     // store swizzle constant = 8*(k>>2)
    const int bk  = t >> 5;          // 0..7 (+8)
    const int bn4 = (t & 31) * 4;    // n quad
    const int gn  = bn + bn4;

    const int KT = K >> 4;           // K multiple of 16
    float4 av[2], bv[2];

    // preload tile 0
#pragma unroll
    for (int p = 0; p < 2; p++) {
        int gm = bm + am + p * 64;
        av[p] = make_float4(0.f, 0.f, 0.f, 0.f);
        if (gm < M) av[p] = *(const float4*)(A + (size_t)gm * K + ak);
        bv[p] = make_float4(0.f, 0.f, 0.f, 0.f);
        if (gn < N) bv[p] = *(const float4*)(B + (size_t)(bk + p * 8) * N + gn);
    }

    for (int kt = 0; kt < KT; kt++) {
        const int buf = kt & 1;
        // store current tile (convert to tf32), swizzled columns
#pragma unroll
        for (int p = 0; p < 2; p++) {
            const int ac = (am + p * 64) ^ axr;     // A col swizzle: 8*(k>>2)=axr
            sm.As[buf][ak + 0][ac] = f2tf32(av[p].x);
            sm.As[buf][ak + 1][ac] = f2tf32(av[p].y);
            sm.As[buf][ak + 2][ac] = f2tf32(av[p].z);
            sm.As[buf][ak + 3][ac] = f2tf32(av[p].w);
            const int bkk = bk + p * 8;
            const int bc  = bn4 ^ ((bkk >> 2) * 8); // B col swizzle (16B-aligned)
            uint4 bq;
            bq.x = f2tf32(bv[p].x);
            bq.y = f2tf32(bv[p].y);
            bq.z = f2tf32(bv[p].z);
            bq.w = f2tf32(bv[p].w);
            *(uint4*)&sm.Bs[buf][bkk][bc] = bq;     // one STS.128, conflict-free
        }
        // prefetch next tile (overlaps with this tile's MMAs)
        if (kt + 1 < KT) {
            const int k0 = (kt + 1) << 4;
#pragma unroll
            for (int p = 0; p < 2; p++) {
                int gm = bm + am + p * 64;
                av[p] = make_float4(0.f, 0.f, 0.f, 0.f);
                if (gm < M) av[p] = *(const float4*)(A + (size_t)gm * K + k0 + ak);
                bv[p] = make_float4(0.f, 0.f, 0.f, 0.f);
                if (gn < N) bv[p] = *(const float4*)(B + (size_t)(k0 + bk + p * 8) * N + gn);
            }
        }
        __syncthreads();   // single barrier/iter: double buffer makes it safe

#pragma unroll
        for (int ks = 0; ks < 2; ks++) {
            const int kb  = ks * 8;
            const int xlo = ks * 16;       // 8*((kb+tid4)>>2)   (tid4<4)
            const int xhi = ks * 16 + 8;   // 8*((kb+tid4+4)>>2)
            uint32_t af[4][4];
#pragma unroll
            for (int mt = 0; mt < 4; mt++) {
                int m = wm + mt * 16;
                af[mt][0] = sm.As[buf][kb + tid4    ][(m + g)     ^ xlo];
                af[mt][1] = sm.As[buf][kb + tid4    ][(m + g + 8) ^ xlo];
                af[mt][2] = sm.As[buf][kb + tid4 + 4][(m + g)     ^ xhi];
                af[mt][3] = sm.As[buf][kb + tid4 + 4][(m + g + 8) ^ xhi];
            }
            uint32_t bf[4][2];
#pragma unroll
            for (int nt = 0; nt < 4; nt++) {
                int n = wn + nt * 8;
                bf[nt][0] = sm.Bs[buf][kb + tid4    ][(n + g) ^ xlo];
                bf[nt][1] = sm.Bs[buf][kb + tid4 + 4][(n + g) ^ xhi];
            }
#pragma unroll
            for (int mt = 0; mt < 4; mt++)
#pragma unroll
                for (int nt = 0; nt < 4; nt++) {
                    float* c = acc[mt][nt];
                    asm volatile(
                        "mma.sync.aligned.m16n8k8.row.col.f32.tf32.tf32.f32 "
                        "{%0,%1,%2,%3}, {%4,%5,%6,%7}, {%8,%9}, {%0,%1,%2,%3};"
                        : "+f"(c[0]), "+f"(c[1]), "+f"(c[2]), "+f"(c[3])
                        : "r"(af[mt][0]), "r"(af[mt][1]), "r"(af[mt][2]), "r"(af[mt][3]),
                          "r"(bf[nt][0]), "r"(bf[nt][1]));
                }
        }
    }

    // epilogue
#pragma unroll
    for (int mt = 0; mt < 4; mt++) {
#pragma unroll
        for (int nt = 0; nt < 4; nt++) {
            int r0 = bm + wm + mt * 16 + g;
            int c  = bn + wn + nt * 8 + 2 * tid4;
            if (c < N) {
                if (r0 < M)
                    *(float2*)(C + (size_t)r0 * N + c) =
                        make_float2(acc[mt][nt][0], acc[mt][nt][1]);
                if (r0 + 8 < M)
                    *(float2*)(C + (size_t)(r0 + 8) * N + c) =
                        make_float2(acc[mt][nt][2], acc[mt][nt][3]);
            }
        }
    }
}

__global__ __launch_bounds__(256) void gemm_tc(const float* __restrict__ A,
                                               const float* __restrict__ B,
                                               float* __restrict__ C,
                                               int M, int K, int N) {
    __shared__ SmemGemm sm;
    gemm_core(sm, A, B, C, M, K, N, blockIdx.y * 128, blockIdx.x * 128);
}

// fused pair: first nx x-blocks compute A@B0 -> C0, rest compute A@B1 -> C1
__global__ __launch_bounds__(256) void gemm_dual(const float* __restrict__ A,
                                                 const float* __restrict__ B0,
                                                 float* __restrict__ C0,
                                                 const float* __restrict__ B1,
                                                 float* __restrict__ C1,
                                                 int M, int K, int N) {
    __shared__ SmemGemm sm;
    const int nx = N / 128;
    const bool second = (blockIdx.x >= nx);
    const float* B = second ? B1 : B0;
    float*       C = second ? C1 : C0;
    const int bn = (second ? (blockIdx.x - nx) : blockIdx.x) * 128;
    gemm_core(sm, A, B, C, M, K, N, blockIdx.y * 128, bn);
}

// ---------------- helpers ----------------
__device__ __forceinline__ float wsum(float v) {
#pragma unroll
    for (int o = 16; o; o >>= 1) v += __shfl_xor_sync(0xffffffffu, v, o);
    return v;
}

// ---------------- GATv2 layer: attention + softmax + aggregate + bias + LN + ELU
// one block (128 threads) per node; warp w handles head w; online softmax,
// with next-edge prefetch to hide L2 gather latency. (round-3 proven version)
__global__ __launch_bounds__(128) void gat_k(const float* __restrict__ xs,
                                             const float* __restrict__ xd,
                                             const float* __restrict__ att,
                                             const float* __restrict__ bias,
                                             const float* __restrict__ gamma,
                                             const float* __restrict__ beta,
                                             const int* __restrict__ off,
                                             const int* __restrict__ csrc,
                                             float* __restrict__ out) {
    const int node = blockIdx.x;
    const int w    = threadIdx.x >> 5;
    const int lane = threadIdx.x & 31;

    const float* ah = att + w * CC;
    const float a0 = ah[lane], a1 = ah[lane + 32], a2 = ah[lane + 64];

    const float* dr = xd + (size_t)node * DD + w * CC;
    const float d0 = dr[lane], d1 = dr[lane + 32], d2 = dr[lane + 64];

    const int s = off[node], e = off[node + 1];

    float mx = -3.0e38f, den = 0.f;
    float acc0 = 0.f, acc1 = 0.f, acc2 = 0.f;

    if (s < e) {
        int sr = __ldg(&csrc[s]);
        const float* xr = xs + (size_t)sr * DD + w * CC;
        float p0 = xr[lane], p1 = xr[lane + 32], p2 = xr[lane + 64];

        for (int j = s; j < e; j++) {
            float s0 = p0, s1 = p1, s2 = p2;
            if (j + 1 < e) {
                int srn = __ldg(&csrc[j + 1]);
                const float* xn = xs + (size_t)srn * DD + w * CC;
                p0 = xn[lane]; p1 = xn[lane + 32]; p2 = xn[lane + 64];
            }
            float m0 = s0 + d0; m0 = (m0 > 0.f) ? m0 : 0.2f * m0;
            float m1 = s1 + d1; m1 = (m1 > 0.f) ? m1 : 0.2f * m1;
            float m2 = s2 + d2; m2 = (m2 > 0.f) ? m2 : 0.2f * m2;
            float p = a0 * m0 + a1 * m1 + a2 * m2;
            p = wsum(p);                       // e_ij, broadcast to all lanes
            float nm = fmaxf(mx, p);
            float so = __expf(mx - nm);        // rescale old state
            float wg = __expf(p - nm);
            den  = den  * so + wg;
            acc0 = acc0 * so + wg * s0;
            acc1 = acc1 * so + wg * s1;
            acc2 = acc2 * so + wg * s2;
            mx = nm;
        }
    }

    float inv = 1.f / (den + 1e-16f);
    int c0 = w * CC + lane;
    float v0 = acc0 * inv + bias[c0];
    float v1 = acc1 * inv + bias[c0 + 32];
    float v2 = acc2 * inv + bias[c0 + 64];

    // block LayerNorm over DD=384, then ELU
    __shared__ float rs[4], rq[4];
    float sm = v0 + v1 + v2;
    float sq = v0 * v0 + v1 * v1 + v2 * v2;
    sm = wsum(sm); sq = wsum(sq);
    if (lane == 0) { rs[w] = sm; rq[w] = sq; }
    __syncthreads();
    float S = rs[0] + rs[1] + rs[2] + rs[3];
    float Q = rq[0] + rq[1] + rq[2] + rq[3];
    float mean = S * (1.0f / DD);
    float var  = Q * (1.0f / DD) - mean * mean;
    float rinv = rsqrtf(var + 1e-5f);

    float* orow = out + (size_t)node * DD;
    float y0 = (v0 - mean) * rinv * gamma[c0]      + beta[c0];
    float y1 = (v1 - mean) * rinv * gamma[c0 + 32] + beta[c0 + 32];
    float y2 = (v2 - mean) * rinv * gamma[c0 + 64] + beta[c0 + 64];
    orow[c0]      = (y0 > 0.f) ? y0 : (__expf(y0) - 1.f);
    orow[c0 + 32] = (y1 > 0.f) ? y1 : (__expf(y1) - 1.f);
    orow[c0 + 64] = (y2 > 0.f) ? y2 : (__expf(y2) - 1.f);
}

// ---------------- classifier tail: relu(t1+bc1) -> LN(96) -> @Wc2 + bc2
__global__ __launch_bounds__(128) void cls_k(const float* __restrict__ t1,
                                             const float* __restrict__ bc1,
                                             const float* __restrict__ gc,
                                             const float* __restrict__ bec,
                                             const float* __restrict__ Wc2,
                                             const float* __restrict__ bc2,
                                             float* __restrict__ out) {
    const int node = blockIdx.x;
    const int t = threadIdx.x, w = t >> 5, lane = t & 31;
    __shared__ float z[CC];
    __shared__ float w2[CC * NCLS];
    __shared__ float rs[4], rq[4];

    for (int i = t; i < CC * NCLS; i += 128) w2[i] = Wc2[i];

    float v = 0.f;
    if (t < CC) v = fmaxf(t1[(size_t)node * CC + t] + bc1[t], 0.f);

    float sm = wsum(v), sq = wsum(v * v);
    if (lane == 0) { rs[w] = sm; rq[w] = sq; }
    __syncthreads();
    float S = rs[0] + rs[1] + rs[2] + rs[3];
    float Q = rq[0] + rq[1] + rq[2] + rq[3];
    float mean = S * (1.0f / CC);
    float var  = Q * (1.0f / CC) - mean * mean;
    float rinv = rsqrtf(var + 1e-5f);
    if (t < CC) z[t] = (v - mean) * rinv * gc[t] + bec[t];
    __syncthreads();

    if (t < NCLS) {
        float o = bc2[t];
#pragma unroll 8
        for (int k = 0; k < CC; k++) o = fmaf(z[k], w2[k * NCLS + t], o);
        out[(size_t)node * NCLS + t] = o;
    }
}

// ---------------- launch ----------------
extern "C" void kernel_launch(void* const* d_in, const int* in_sizes, int n_in,
                              void* d_out, int out_size) {
    const float* x   = (const float*)d_in[0];
    const int*   ei  = (const int*)d_in[1];
    const float* Wsrc[3] = {(const float*)d_in[2],  (const float*)d_in[8],  (const float*)d_in[14]};
    const float* Wdst[3] = {(const float*)d_in[3],  (const float*)d_in[9],  (const float*)d_in[15]};
    const float* attp[3] = {(const float*)d_in[4],  (const float*)d_in[10], (const float*)d_in[16]};
    const float* bb[3]   = {(const float*)d_in[5],  (const float*)d_in[11], (const float*)d_in[17]};
    const float* gg[3]   = {(const float*)d_in[6],  (const float*)d_in[12], (const float*)d_in[18]};
    const float* be[3]   = {(const float*)d_in[7],  (const float*)d_in[13], (const float*)d_in[19]};
    const float* Wc1 = (const float*)d_in[20];
    const float* bc1 = (const float*)d_in[21];
    const float* gc  = (const float*)d_in[22];
    const float* bec = (const float*)d_in[23];
    const float* Wc2 = (const float*)d_in[24];
    const float* bc2 = (const float*)d_in[25];
    float* out = (float*)d_out;

    float *xs, *xd, *h, *t1;
    int *off, *cnt, *cur, *eid, *csrc;
    cudaGetSymbolAddress((void**)&xs,   g_xs);
    cudaGetSymbolAddress((void**)&xd,   g_xd);
    cudaGetSymbolAddress((void**)&h,    g_h);
    cudaGetSymbolAddress((void**)&t1,   g_t1);
    cudaGetSymbolAddress((void**)&off,  g_off);
    cudaGetSymbolAddress((void**)&cnt,  g_cnt);
    cudaGetSymbolAddress((void**)&cur,  g_cur);
    cudaGetSymbolAddress((void**)&eid,  g_eid);
    cudaGetSymbolAddress((void**)&csrc, g_csrc);

    const int* src = ei;
    const int* dst = ei + EE;

    dim3 gd(2 * (DD / 128), (NN + 127) / 128); // 6 x 391

    // CSR build. cnt is zero at entry (zero-init first call; scan_k re-zeroes
    // it each call after reading, so no memset launch is needed).
    hist_k<<<(EE + 255) / 256, 256>>>(dst, cnt);                 // launch 0
    scan_k<<<1, 1024>>>(cnt, off, cur);                          // launch 1
    scatter_k<<<(EE + 255) / 256, 256>>>(dst, cur, eid);         // launch 2
    sortsrc_k<<<(NN + 127) / 128, 128>>>(src, off, eid, csrc);   // launch 3

    // layer 0 (fused GEMM pair at slot 4, gat at slot 5 -> ncu -s 5 -c 1
    // profiles gat_k next time)
    gemm_dual<<<gd, 256>>>(x, Wsrc[0], xs, Wdst[0], xd, NN, FIN, DD); // 4
    gat_k<<<NN, 128>>>(xs, xd, attp[0], bb[0], gg[0], be[0], off, csrc, h); // 5

    // layers 1..2 (fused GEMM pair)
    for (int l = 1; l < 3; l++) {
        gemm_dual<<<gd, 256>>>(h, Wsrc[l], xs, Wdst[l], xd, NN, DD, DD);
        gat_k<<<NN, 128>>>(xs, xd, attp[l], bb[l], gg[l], be[l], off, csrc, h);
    }

    // classifier
    dim3 g2(1, (NN + 127) / 128);
    gemm_tc<<<g2, 256>>>(h, Wc1, t1, NN, DD, CC);
    cls_k<<<NN, 128>>>(t1, bc1, gc, bec, Wc2, bc2, out);
}

// round 9
// speedup vs baseline: 1.1641x; 1.1641x over previous
#include <cuda_runtime.h>
#include <cstdint>

#define NN    50000
#define EE    800000
#define FIN   80
#define HH    4
#define CC    96
#define DD    384
#define NCLS  20

// weight offsets in the converted-weights buffer (floats)
#define W_S0  0
#define W_D0  30720
#define W_S1  61440
#define W_D1  208896
#define W_S2  356352
#define W_D2  503808
#define W_C1  651264
#define W_TOT 688128

// ---------------- device scratch (no allocations allowed) ----------------
__device__ float g_xs[(size_t)NN * DD];
__device__ float g_xd[(size_t)NN * DD];
__device__ float g_h [(size_t)NN * DD];
__device__ float g_t1[(size_t)NN * CC];
__device__ float g_xc[(size_t)NN * FIN];   // tf32-rounded x
__device__ float g_wc[W_TOT];              // tf32-rounded weights
__device__ int   g_off[NN + 1];
__device__ int   g_cur[NN];
__device__ int   g_eid[EE];
__device__ int   g_csrc[EE];

__device__ __forceinline__ uint32_t f2tf32(float f) {
    uint32_t r;
    asm("cvt.rna.tf32.f32 %0, %1;" : "=r"(r) : "f"(f));
    return r;
}
__device__ __forceinline__ float tf32r(float f) { return __uint_as_float(f2tf32(f)); }

// ---------------- CSR build (R6-proven) ----------------
__global__ void hist_k(const int* __restrict__ dst, int* __restrict__ cnt) {
    int i = blockIdx.x * blockDim.x + threadIdx.x;
    if (i < EE) atomicAdd(&cnt[dst[i]], 1);
}

__global__ void scan_k(const int* __restrict__ cnt, int* __restrict__ off,
                       int* __restrict__ cur) {
    __shared__ int wsums[32];
    __shared__ int carry_s;
    const int t = threadIdx.x, lane = t & 31, wp = t >> 5;
    if (t == 0) carry_s = 0;
    __syncthreads();
    for (int base = 0; base < NN; base += 1024) {
        int i = base + t;
        int v = (i < NN) ? cnt[i] : 0;
        int x = v;
#pragma unroll
        for (int o = 1; o < 32; o <<= 1) {
            int y = __shfl_up_sync(0xffffffffu, x, o);
            if (lane >= o) x += y;
        }
        if (lane == 31) wsums[wp] = x;
        __syncthreads();
        if (wp == 0) {
            int ws = wsums[lane];
#pragma unroll
            for (int o = 1; o < 32; o <<= 1) {
                int y = __shfl_up_sync(0xffffffffu, ws, o);
                if (lane >= o) ws += y;
            }
            wsums[lane] = ws;
        }
        __syncthreads();
        int add = (wp > 0) ? wsums[wp - 1] : 0;
        int excl = carry_s + x + add - v;
        if (i < NN) { off[i] = excl; cur[i] = excl; }
        int tot = wsums[31];
        __syncthreads();
        if (t == 0) carry_s += tot;
        __syncthreads();
    }
    if (t == 0) off[NN] = carry_s;
}

__global__ void scatter_k(const int* __restrict__ dst, int* __restrict__ cur,
                          int* __restrict__ eid) {
    int i = blockIdx.x * blockDim.x + threadIdx.x;
    if (i < EE) {
        int d = dst[i];
        int p = atomicAdd(&cur[d], 1);
        eid[p] = i;
    }
}

__global__ void sortsrc_k(const int* __restrict__ srcArr, const int* __restrict__ off,
                          int* __restrict__ eid, int* __restrict__ csrc) {
    int v = blockIdx.x * blockDim.x + threadIdx.x;
    if (v >= NN) return;
    int s = off[v], e = off[v + 1];
    for (int i = s + 1; i < e; i++) {
        int key = eid[i];
        int j = i - 1;
        while (j >= s && eid[j] > key) { eid[j + 1] = eid[j]; j--; }
        eid[j + 1] = key;
    }
    for (int i = s; i < e; i++) csrc[i] = srcArr[eid[i]];
}

// ---------------- tf32 pre-conversion ----------------
__global__ void cvtx_k(const float* __restrict__ in, float* __restrict__ outp, int n) {
    int i = blockIdx.x * blockDim.x + threadIdx.x;
    if (i < n) outp[i] = tf32r(in[i]);
}

__global__ void cvtw_k(const float* w0, const float* w1, const float* w2,
                       const float* w3, const float* w4, const float* w5,
                       const float* w6, float* __restrict__ outp) {
    int i = blockIdx.x * blockDim.x + threadIdx.x;
    if (i >= W_TOT) return;
    const float* p;
    int idx = i;
    if      (i < W_D0) { p = w0; idx = i - W_S0; }
    else if (i < W_S1) { p = w1; idx = i - W_D0; }
    else if (i < W_D1) { p = w2; idx = i - W_S1; }
    else if (i < W_S2) { p = w3; idx = i - W_D1; }
    else if (i < W_D2) { p = w4; idx = i - W_S2; }
    else if (i < W_C1) { p = w5; idx = i - W_D2; }
    else               { p = w6; idx = i - W_C1; }
    outp[i] = tf32r(p[idx]);
}

// ---------------- cp.async tf32 GEMM: C[M,N] = A[M,K] @ B[K,N] ----------------
// A, B already tf32-rounded in gmem. 128x128 CTA tile, 8 warps (64x32 each),
// BK=16, mma.m16n8k8.tf32. 2-stage cp.async pipeline, no register staging,
// no conversion in the hot loop.
// SMEM: A row-major [128][20] (pad->bank-free frag loads), B [16][136].
#define ASTG (128 * 20)
#define BSTG (16 * 136)

template<int KT>
__device__ __forceinline__ void gemm_ca_core(float* Asm, float* Bsm,
                                             const float* __restrict__ A,
                                             const float* __restrict__ B,
                                             float* __restrict__ C,
                                             int M, int N, int bm, int bn) {
    const int K    = KT * 16;
    const int t    = threadIdx.x;
    const int lane = t & 31;
    const int w    = t >> 5;
    const int wm   = (w & 1) * 64;
    const int wn   = (w >> 1) * 32;
    const int g    = lane >> 2;
    const int tid4 = lane & 3;

    float acc[4][4][4];
#pragma unroll
    for (int i = 0; i < 4; i++)
#pragma unroll
        for (int j = 0; j < 4; j++)
#pragma unroll
            for (int r = 0; r < 4; r++) acc[i][j][r] = 0.f;

    // ---- async-copy mappings (256 threads, 4x 16B chunks each per ktile) ----
    const int am  = t >> 2;          // A row 0..63 (+64)
    const int ac4 = (t & 3) * 4;     // k-word within row
    const int bkr = t >> 5;          // B row 0..7 (+8)
    const int bnc = (t & 31) * 4;    // n-word

    const int gm0 = bm + am, gm1 = bm + am + 64;
    const int asz0 = (gm0 < M) ? 16 : 0;
    const int asz1 = (gm1 < M) ? 16 : 0;
    const float* agp0 = A + (size_t)(asz0 ? gm0 : 0) * K + ac4;
    const float* agp1 = A + (size_t)(asz1 ? gm1 : 0) * K + ac4;

    const int gn  = bn + bnc;
    const int bsz = (gn < N) ? 16 : 0;
    const float* bgp0 = B + (size_t)bkr * N + (bsz ? gn : 0);
    const float* bgp1 = B + (size_t)(bkr + 8) * N + (bsz ? gn : 0);

    const uint32_t sA = (uint32_t)__cvta_generic_to_shared(Asm);
    const uint32_t sB = (uint32_t)__cvta_generic_to_shared(Bsm);
    const uint32_t ad0 = sA + (uint32_t)(am * 20 + ac4) * 4;
    const uint32_t ad1 = sA + (uint32_t)((am + 64) * 20 + ac4) * 4;
    const uint32_t bd0 = sB + (uint32_t)(bkr * 136 + bnc) * 4;
    const uint32_t bd1 = sB + (uint32_t)((bkr + 8) * 136 + bnc) * 4;

#define COPY_TILE(stg, ktt)                                                         \
    do {                                                                            \
        const uint32_t soa = (uint32_t)(stg) * (ASTG * 4);                          \
        const uint32_t sob = (uint32_t)(stg) * (BSTG * 4);                          \
        asm volatile("cp.async.cg.shared.global [%0], [%1], 16, %2;"                \
                     :: "r"(ad0 + soa), "l"(agp0 + (ktt) * 16), "r"(asz0));         \
        asm volatile("cp.async.cg.shared.global [%0], [%1], 16, %2;"                \
                     :: "r"(ad1 + soa), "l"(agp1 + (ktt) * 16), "r"(asz1));         \
        asm volatile("cp.async.cg.shared.global [%0], [%1], 16, %2;"                \
                     :: "r"(bd0 + sob), "l"(bgp0 + (size_t)(ktt) * 16 * N), "r"(bsz)); \
        asm volatile("cp.async.cg.shared.global [%0], [%1], 16, %2;"                \
                     :: "r"(bd1 + sob), "l"(bgp1 + (size_t)(ktt) * 16 * N), "r"(bsz)); \
    } while (0)

    COPY_TILE(0, 0);
    asm volatile("cp.async.commit_group;");

#pragma unroll 2
    for (int kt = 0; kt < KT; kt++) {
        if (kt + 1 < KT) {
            COPY_TILE((kt + 1) & 1, kt + 1);
            asm volatile("cp.async.commit_group;");
            asm volatile("cp.async.wait_group 1;");
        } else {
            asm volatile("cp.async.wait_group 0;");
        }
        __syncthreads();

        const float* As_ = Asm + (kt & 1) * ASTG;
        const float* Bs_ = Bsm + (kt & 1) * BSTG;
#pragma unroll
        for (int ks = 0; ks < 2; ks++) {
            const int kb = ks * 8;
            uint32_t af[4][4];
#pragma unroll
            for (int mt = 0; mt < 4; mt++) {
                const int m = wm + mt * 16 + g;
                af[mt][0] = __float_as_uint(As_[m * 20 + kb + tid4]);
                af[mt][1] = __float_as_uint(As_[(m + 8) * 20 + kb + tid4]);
                af[mt][2] = __float_as_uint(As_[m * 20 + kb + tid4 + 4]);
                af[mt][3] = __float_as_uint(As_[(m + 8) * 20 + kb + tid4 + 4]);
            }
            uint32_t bf[4][2];
#pragma unroll
            for (int nt = 0; nt < 4; nt++) {
                const int n = wn + nt * 8 + g;
                bf[nt][0] = __float_as_uint(Bs_[(kb + tid4) * 136 + n]);
                bf[nt][1] = __float_as_uint(Bs_[(kb + tid4 + 4) * 136 + n]);
            }
#pragma unroll
            for (int mt = 0; mt < 4; mt++)
#pragma unroll
                for (int nt = 0; nt < 4; nt++) {
                    float* c = acc[mt][nt];
                    asm volatile(
                        "mma.sync.aligned.m16n8k8.row.col.f32.tf32.tf32.f32 "
                        "{%0,%1,%2,%3}, {%4,%5,%6,%7}, {%8,%9}, {%0,%1,%2,%3};"
                        : "+f"(c[0]), "+f"(c[1]), "+f"(c[2]), "+f"(c[3])
                        : "r"(af[mt][0]), "r"(af[mt][1]), "r"(af[mt][2]), "r"(af[mt][3]),
                          "r"(bf[nt][0]), "r"(bf[nt][1]));
                }
        }
        __syncthreads();
    }
#undef COPY_TILE

    // epilogue
#pragma unroll
    for (int mt = 0; mt < 4; mt++) {
#pragma unroll
        for (int nt = 0; nt < 4; nt++) {
            int r0 = bm + wm + mt * 16 + g;
            int c  = bn + wn + nt * 8 + 2 * tid4;
            if (c < N) {
                if (r0 < M)
                    *(float2*)(C + (size_t)r0 * N + c) =
                        make_float2(acc[mt][nt][0], acc[mt][nt][1]);
                if (r0 + 8 < M)
                    *(float2*)(C + (size_t)(r0 + 8) * N + c) =
                        make_float2(acc[mt][nt][2], acc[mt][nt][3]);
            }
        }
    }
}

template<int KT>
__global__ __launch_bounds__(256, 2) void gemm_ca(const float* __restrict__ A,
                                                  const float* __restrict__ B,
                                                  float* __restrict__ C,
                                                  int M, int N) {
    __shared__ float Asm[2 * ASTG];
    __shared__ float Bsm[2 * BSTG];
    gemm_ca_core<KT>(Asm, Bsm, A, B, C, M, N, blockIdx.y * 128, blockIdx.x * 128);
}

// fused pair: first nx x-blocks compute A@B0 -> C0, rest A@B1 -> C1
template<int KT>
__global__ __launch_bounds__(256, 2) void gemm_dual_ca(const float* __restrict__ A,
                                                       const float* __restrict__ B0,
                                                       float* __restrict__ C0,
                                                       const float* __restrict__ B1,
                                                       float* __restrict__ C1,
                                                       int M, int N) {
    __shared__ float Asm[2 * ASTG];
    __shared__ float Bsm[2 * BSTG];
    const int nx = N / 128;
    const bool second = (blockIdx.x >= nx);
    const float* B = second ? B1 : B0;
    float*       C = second ? C1 : C0;
    const int bn = (second ? (blockIdx.x - nx) : blockIdx.x) * 128;
    gemm_ca_core<KT>(Asm, Bsm, A, B, C, M, N, blockIdx.y * 128, bn);
}

// ---------------- helpers ----------------
__device__ __forceinline__ float wsum(float v) {
#pragma unroll
    for (int o = 16; o; o >>= 1) v += __shfl_xor_sync(0xffffffffu, v, o);
    return v;
}

// ---------------- GATv2 layer (R3/R6-proven) + tf32-rounded h output ----------------
__global__ __launch_bounds__(128) void gat_k(const float* __restrict__ xs,
                                             const float* __restrict__ xd,
                                             const float* __restrict__ att,
                                             const float* __restrict__ bias,
                                             const float* __restrict__ gamma,
                                             const float* __restrict__ beta,
                                             const int* __restrict__ off,
                                             const int* __restrict__ csrc,
                                             float* __restrict__ out) {
    const int node = blockIdx.x;
    const int w    = threadIdx.x >> 5;
    const int lane = threadIdx.x & 31;

    const float* ah = att + w * CC;
    const float a0 = ah[lane], a1 = ah[lane + 32], a2 = ah[lane + 64];

    const float* dr = xd + (size_t)node * DD + w * CC;
    const float d0 = dr[lane], d1 = dr[lane + 32], d2 = dr[lane + 64];

    const int s = off[node], e = off[node + 1];

    float mx = -3.0e38f, den = 0.f;
    float acc0 = 0.f, acc1 = 0.f, acc2 = 0.f;

    if (s < e) {
        int sr = __ldg(&csrc[s]);
        const float* xr = xs + (size_t)sr * DD + w * CC;
        float p0 = xr[lane], p1 = xr[lane + 32], p2 = xr[lane + 64];

        for (int j = s; j < e; j++) {
            float s0 = p0, s1 = p1, s2 = p2;
            if (j + 1 < e) {
                int srn = __ldg(&csrc[j + 1]);
                const float* xn = xs + (size_t)srn * DD + w * CC;
                p0 = xn[lane]; p1 = xn[lane + 32]; p2 = xn[lane + 64];
            }
            float m0 = s0 + d0; m0 = (m0 > 0.f) ? m0 : 0.2f * m0;
            float m1 = s1 + d1; m1 = (m1 > 0.f) ? m1 : 0.2f * m1;
            float m2 = s2 + d2; m2 = (m2 > 0.f) ? m2 : 0.2f * m2;
            float p = a0 * m0 + a1 * m1 + a2 * m2;
            p = wsum(p);
            float nm = fmaxf(mx, p);
            float so = __expf(mx - nm);
            float wg = __expf(p - nm);
            den  = den  * so + wg;
            acc0 = acc0 * so + wg * s0;
            acc1 = acc1 * so + wg * s1;
            acc2 = acc2 * so + wg * s2;
            mx = nm;
        }
    }

    float inv = 1.f / (den + 1e-16f);
    int c0 = w * CC + lane;
    float v0 = acc0 * inv + bias[c0];
    float v1 = acc1 * inv + bias[c0 + 32];
    float v2 = acc2 * inv + bias[c0 + 64];

    __shared__ float rs[4], rq[4];
    float sm = v0 + v1 + v2;
    float sq = v0 * v0 + v1 * v1 + v2 * v2;
    sm = wsum(sm); sq = wsum(sq);
    if (lane == 0) { rs[w] = sm; rq[w] = sq; }
    __syncthreads();
    float S = rs[0] + rs[1] + rs[2] + rs[3];
    float Q = rq[0] + rq[1] + rq[2] + rq[3];
    float mean = S * (1.0f / DD);
    float var  = Q * (1.0f / DD) - mean * mean;
    float rinv = rsqrtf(var + 1e-5f);

    float* orow = out + (size_t)node * DD;
    float y0 = (v0 - mean) * rinv * gamma[c0]      + beta[c0];
    float y1 = (v1 - mean) * rinv * gamma[c0 + 32] + beta[c0 + 32];
    float y2 = (v2 - mean) * rinv * gamma[c0 + 64] + beta[c0 + 64];
    y0 = (y0 > 0.f) ? y0 : (__expf(y0) - 1.f);
    y1 = (y1 > 0.f) ? y1 : (__expf(y1) - 1.f);
    y2 = (y2 > 0.f) ? y2 : (__expf(y2) - 1.f);
    // h feeds only GEMM A operands -> pre-round to tf32 (same cvt the GEMM
    // used to apply; numerics identical)
    orow[c0]      = tf32r(y0);
    orow[c0 + 32] = tf32r(y1);
    orow[c0 + 64] = tf32r(y2);
}

// ---------------- classifier tail: relu(t1+bc1) -> LN(96) -> @Wc2 + bc2
__global__ __launch_bounds__(128) void cls_k(const float* __restrict__ t1,
                                             const float* __restrict__ bc1,
                                             const float* __restrict__ gc,
                                             const float* __restrict__ bec,
                                             const float* __restrict__ Wc2,
                                             const float* __restrict__ bc2,
                                             float* __restrict__ out) {
    const int node = blockIdx.x;
    const int t = threadIdx.x, w = t >> 5, lane = t & 31;
    __shared__ float z[CC];
    __shared__ float w2[CC * NCLS];
    __shared__ float rs[4], rq[4];

    for (int i = t; i < CC * NCLS; i += 128) w2[i] = Wc2[i];

    float v = 0.f;
    if (t < CC) v = fmaxf(t1[(size_t)node * CC + t] + bc1[t], 0.f);

    float sm = wsum(v), sq = wsum(v * v);
    if (lane == 0) { rs[w] = sm; rq[w] = sq; }
    __syncthreads();
    float S = rs[0] + rs[1] + rs[2] + rs[3];
    float Q = rq[0] + rq[1] + rq[2] + rq[3];
    float mean = S * (1.0f / CC);
    float var  = Q * (1.0f / CC) - mean * mean;
    float rinv = rsqrtf(var + 1e-5f);
    if (t < CC) z[t] = (v - mean) * rinv * gc[t] + bec[t];
    __syncthreads();

    if (t < NCLS) {
        float o = bc2[t];
#pragma unroll 8
        for (int k = 0; k < CC; k++) o = fmaf(z[k], w2[k * NCLS + t], o);
        out[(size_t)node * NCLS + t] = o;
    }
}

// ---------------- launch ----------------
extern "C" void kernel_launch(void* const* d_in, const int* in_sizes, int n_in,
                              void* d_out, int out_size) {
    const float* x   = (const float*)d_in[0];
    const int*   ei  = (const int*)d_in[1];
    const float* Wsrc[3] = {(const float*)d_in[2],  (const float*)d_in[8],  (const float*)d_in[14]};
    const float* Wdst[3] = {(const float*)d_in[3],  (const float*)d_in[9],  (const float*)d_in[15]};
    const float* attp[3] = {(const float*)d_in[4],  (const float*)d_in[10], (const float*)d_in[16]};
    const float* bb[3]   = {(const float*)d_in[5],  (const float*)d_in[11], (const float*)d_in[17]};
    const float* gg[3]   = {(const float*)d_in[6],  (const float*)d_in[12], (const float*)d_in[18]};
    const float* be[3]   = {(const float*)d_in[7],  (const float*)d_in[13], (const float*)d_in[19]};
    const float* Wc1 = (const float*)d_in[20];
    const float* bc1 = (const float*)d_in[21];
    const float* gc  = (const float*)d_in[22];
    const float* bec = (const float*)d_in[23];
    const float* Wc2 = (const float*)d_in[24];
    const float* bc2 = (const float*)d_in[25];
    float* out = (float*)d_out;

    float *xs, *xd, *h, *t1, *xc, *wc;
    int *off, *cur, *eid, *csrc;
    cudaGetSymbolAddress((void**)&xs,   g_xs);
    cudaGetSymbolAddress((void**)&xd,   g_xd);
    cudaGetSymbolAddress((void**)&h,    g_h);
    cudaGetSymbolAddress((void**)&t1,   g_t1);
    cudaGetSymbolAddress((void**)&xc,   g_xc);
    cudaGetSymbolAddress((void**)&wc,   g_wc);
    cudaGetSymbolAddress((void**)&off,  g_off);
    cudaGetSymbolAddress((void**)&cur,  g_cur);
    cudaGetSymbolAddress((void**)&eid,  g_eid);
    cudaGetSymbolAddress((void**)&csrc, g_csrc);

    const int* src = ei;
    const int* dst = ei + EE;

    dim3 gd(2 * (DD / 128), (NN + 127) / 128); // 6 x 391

    // CSR build (R6-proven)
    cudaMemsetAsync(cur, 0, NN * sizeof(int));
    hist_k<<<(EE + 255) / 256, 256>>>(dst, cur);
    scan_k<<<1, 1024>>>(cur, off, cur);
    scatter_k<<<(EE + 255) / 256, 256>>>(dst, cur, eid);
    sortsrc_k<<<(NN + 127) / 128, 128>>>(src, off, eid, csrc);

    // tf32 pre-conversion (x + all GEMM weights)
    cvtx_k<<<(NN * FIN + 255) / 256, 256>>>(x, xc, NN * FIN);
    cvtw_k<<<(W_TOT + 255) / 256, 256>>>(Wsrc[0], Wdst[0], Wsrc[1], Wdst[1],
                                         Wsrc[2], Wdst[2], Wc1, wc);

    // layer 0 (K=80 -> KT=5)
    gemm_dual_ca<5><<<gd, 256>>>(xc, wc + W_S0, xs, wc + W_D0, xd, NN, DD);
    gat_k<<<NN, 128>>>(xs, xd, attp[0], bb[0], gg[0], be[0], off, csrc, h);

    // layers 1..2 (K=384 -> KT=24)
    gemm_dual_ca<24><<<gd, 256>>>(h, wc + W_S1, xs, wc + W_D1, xd, NN, DD);
    gat_k<<<NN, 128>>>(xs, xd, attp[1], bb[1], gg[1], be[1], off, csrc, h);
    gemm_dual_ca<24><<<gd, 256>>>(h, wc + W_S2, xs, wc + W_D2, xd, NN, DD);
    gat_k<<<NN, 128>>>(xs, xd, attp[2], bb[2], gg[2], be[2], off, csrc, h);

    // classifier (N=96, zfill guards handle the partial tile)
    dim3 g2(1, (NN + 127) / 128);
    gemm_ca<24><<<g2, 256>>>(h, wc + W_C1, t1, NN, CC);
    cls_k<<<NN, 128>>>(t1, bc1, gc, bec, Wc2, bc2, out);
}

// round 13
// speedup vs baseline: 1.1670x; 1.0025x over previous
#include <cuda_runtime.h>
#include <cstdint>

#define NN    50000
#define EE    800000
#define FIN   80
#define HH    4
#define CC    96
#define DD    384
#define NCLS  20

// weight offsets in the converted-weights buffer (floats)
#define W_S0  0
#define W_D0  30720
#define W_S1  61440
#define W_D1  208896
#define W_S2  356352
#define W_D2  503808
#define W_C1  651264
#define W_TOT 688128

// ---------------- device scratch (no allocations allowed) ----------------
__device__ float g_xs[(size_t)NN * DD];
__device__ float g_xd[(size_t)NN * DD];
__device__ float g_h [(size_t)NN * DD];
__device__ float g_t1[(size_t)NN * CC];
__device__ float g_xc[(size_t)NN * FIN];   // tf32-rounded x
__device__ float g_wc[W_TOT];              // tf32-rounded weights
__device__ int   g_off[NN + 1];
__device__ int   g_cur[NN];
__device__ int   g_eid[EE];
__device__ int   g_csrc[EE];

__device__ __forceinline__ uint32_t f2tf32(float f) {
    uint32_t r;
    asm("cvt.rna.tf32.f32 %0, %1;" : "=r"(r) : "f"(f));
    return r;
}
__device__ __forceinline__ float tf32r(float f) { return __uint_as_float(f2tf32(f)); }

// ---------------- CSR build (proven) ----------------
__global__ void hist_k(const int* __restrict__ dst, int* __restrict__ cnt) {
    int i = blockIdx.x * blockDim.x + threadIdx.x;
    if (i < EE) atomicAdd(&cnt[dst[i]], 1);
}

// warp-shuffle scan; writes exclusive offsets to off AND cur
__global__ void scan_k(const int* __restrict__ cnt, int* __restrict__ off,
                       int* __restrict__ cur) {
    __shared__ int wsums[32];
    __shared__ int carry_s;
    const int t = threadIdx.x, lane = t & 31, wp = t >> 5;
    if (t == 0) carry_s = 0;
    __syncthreads();
    for (int base = 0; base < NN; base += 1024) {
        int i = base + t;
        int v = (i < NN) ? cnt[i] : 0;
        int x = v;
#pragma unroll
        for (int o = 1; o < 32; o <<= 1) {
            int y = __shfl_up_sync(0xffffffffu, x, o);
            if (lane >= o) x += y;
        }
        if (lane == 31) wsums[wp] = x;
        __syncthreads();
        if (wp == 0) {
            int ws = wsums[lane];
#pragma unroll
            for (int o = 1; o < 32; o <<= 1) {
                int y = __shfl_up_sync(0xffffffffu, ws, o);
                if (lane >= o) ws += y;
            }
            wsums[lane] = ws;
        }
        __syncthreads();
        int add = (wp > 0) ? wsums[wp - 1] : 0;
        int excl = carry_s + x + add - v;
        if (i < NN) { off[i] = excl; cur[i] = excl; }
        int tot = wsums[31];
        __syncthreads();
        if (t == 0) carry_s += tot;
        __syncthreads();
    }
    if (t == 0) off[NN] = carry_s;
}

__global__ void scatter_k(const int* __restrict__ dst, int* __restrict__ cur,
                          int* __restrict__ eid) {
    int i = blockIdx.x * blockDim.x + threadIdx.x;
    if (i < EE) {
        int d = dst[i];
        int p = atomicAdd(&cur[d], 1);
        eid[p] = i;
    }
}

__global__ void sortsrc_k(const int* __restrict__ srcArr, const int* __restrict__ off,
                          int* __restrict__ eid, int* __restrict__ csrc) {
    int v = blockIdx.x * blockDim.x + threadIdx.x;
    if (v >= NN) return;
    int s = off[v], e = off[v + 1];
    for (int i = s + 1; i < e; i++) {
        int key = eid[i];
        int j = i - 1;
        while (j >= s && eid[j] > key) { eid[j + 1] = eid[j]; j--; }
        eid[j + 1] = key;
    }
    for (int i = s; i < e; i++) csrc[i] = srcArr[eid[i]];
}

// ---------------- tf32 pre-conversion ----------------
__global__ void cvtx_k(const float* __restrict__ in, float* __restrict__ outp, int n) {
    int i = blockIdx.x * blockDim.x + threadIdx.x;
    if (i < n) outp[i] = tf32r(in[i]);
}

// ---------------- cp.async tf32 GEMM: C[M,N] = A[M,K] @ B[K,N] ----------------
// A, B already tf32-rounded in gmem. 128x128 CTA tile, 8 warps (64x32 each),
// BK=16, mma.m16n8k8.tf32. 2-stage pipeline with ONE barrier per k-tile:
//   wait_group 0 -> sync -> issue copy(kt+1) -> compute(kt)
// The single sync both publishes tile kt and drains compute(kt-1) on the
// stage that copy(kt+1) overwrites, so the trailing barrier is unnecessary.
#define ASTG (128 * 20)
#define BSTG (16 * 136)

template<int KT>
__device__ __forceinline__ void gemm_ca_core(float* Asm, float* Bsm,
                                             const float* __restrict__ A,
                                             const float* __restrict__ B,
                                             float* __restrict__ C,
                                             int M, int N, int bm, int bn) {
    const int K    = KT * 16;
    const int t    = threadIdx.x;
    const int lane = t & 31;
    const int w    = t >> 5;
    const int wm   = (w & 1) * 64;
    const int wn   = (w >> 1) * 32;
    const int g    = lane >> 2;
    const int tid4 = lane & 3;

    float acc[4][4][4];
#pragma unroll
    for (int i = 0; i < 4; i++)
#pragma unroll
        for (int j = 0; j < 4; j++)
#pragma unroll
            for (int r = 0; r < 4; r++) acc[i][j][r] = 0.f;

    // ---- async-copy mappings (256 threads, 4x 16B chunks each per ktile) ----
    const int am  = t >> 2;          // A row 0..63 (+64)
    const int ac4 = (t & 3) * 4;     // k-word within row
    const int bkr = t >> 5;          // B row 0..7 (+8)
    const int bnc = (t & 31) * 4;    // n-word

    const int gm0 = bm + am, gm1 = bm + am + 64;
    const int asz0 = (gm0 < M) ? 16 : 0;
    const int asz1 = (gm1 < M) ? 16 : 0;
    const float* agp0 = A + (size_t)(asz0 ? gm0 : 0) * K + ac4;
    const float* agp1 = A + (size_t)(asz1 ? gm1 : 0) * K + ac4;

    const int gn  = bn + bnc;
    const int bsz = (gn < N) ? 16 : 0;
    const float* bgp0 = B + (size_t)bkr * N + (bsz ? gn : 0);
    const float* bgp1 = B + (size_t)(bkr + 8) * N + (bsz ? gn : 0);

    const uint32_t sA = (uint32_t)__cvta_generic_to_shared(Asm);
    const uint32_t sB = (uint32_t)__cvta_generic_to_shared(Bsm);
    const uint32_t ad0 = sA + (uint32_t)(am * 20 + ac4) * 4;
    const uint32_t ad1 = sA + (uint32_t)((am + 64) * 20 + ac4) * 4;
    const uint32_t bd0 = sB + (uint32_t)(bkr * 136 + bnc) * 4;
    const uint32_t bd1 = sB + (uint32_t)((bkr + 8) * 136 + bnc) * 4;

#define COPY_TILE(stg, ktt)                                                         \
    do {                                                                            \
        const uint32_t soa = (uint32_t)(stg) * (ASTG * 4);                          \
        const uint32_t sob = (uint32_t)(stg) * (BSTG * 4);                          \
        asm volatile("cp.async.cg.shared.global [%0], [%1], 16, %2;"                \
                     :: "r"(ad0 + soa), "l"(agp0 + (ktt) * 16), "r"(asz0));         \
        asm volatile("cp.async.cg.shared.global [%0], [%1], 16, %2;"                \
                     :: "r"(ad1 + soa), "l"(agp1 + (ktt) * 16), "r"(asz1));         \
        asm volatile("cp.async.cg.shared.global [%0], [%1], 16, %2;"                \
                     :: "r"(bd0 + sob), "l"(bgp0 + (size_t)(ktt) * 16 * N), "r"(bsz)); \
        asm volatile("cp.async.cg.shared.global [%0], [%1], 16, %2;"                \
                     :: "r"(bd1 + sob), "l"(bgp1 + (size_t)(ktt) * 16 * N), "r"(bsz)); \
    } while (0)

    COPY_TILE(0, 0);
    asm volatile("cp.async.commit_group;");

#pragma unroll 2
    for (int kt = 0; kt < KT; kt++) {
        asm volatile("cp.async.wait_group 0;");   // tile kt resident (this thread)
        __syncthreads();                          // all threads' tile kt + compute(kt-1) drained
        if (kt + 1 < KT) {
            COPY_TILE((kt + 1) & 1, kt + 1);      // overwrites stage (kt-1)&1: safe post-sync
            asm volatile("cp.async.commit_group;");
        }

        const float* As_ = Asm + (kt & 1) * ASTG;
        const float* Bs_ = Bsm + (kt & 1) * BSTG;
#pragma unroll
        for (int ks = 0; ks < 2; ks++) {
            const int kb = ks * 8;
            uint32_t af[4][4];
#pragma unroll
            for (int mt = 0; mt < 4; mt++) {
                const int m = wm + mt * 16 + g;
                af[mt][0] = __float_as_uint(As_[m * 20 + kb + tid4]);
                af[mt][1] = __float_as_uint(As_[(m + 8) * 20 + kb + tid4]);
                af[mt][2] = __float_as_uint(As_[m * 20 + kb + tid4 + 4]);
                af[mt][3] = __float_as_uint(As_[(m + 8) * 20 + kb + tid4 + 4]);
            }
            uint32_t bf[4][2];
#pragma unroll
            for (int nt = 0; nt < 4; nt++) {
                const int n = wn + nt * 8 + g;
                bf[nt][0] = __float_as_uint(Bs_[(kb + tid4) * 136 + n]);
                bf[nt][1] = __float_as_uint(Bs_[(kb + tid4 + 4) * 136 + n]);
            }
#pragma unroll
            for (int mt = 0; mt < 4; mt++)
#pragma unroll
                for (int nt = 0; nt < 4; nt++) {
                    float* c = acc[mt][nt];
                    asm volatile(
                        "mma.sync.aligned.m16n8k8.row.col.f32.tf32.tf32.f32 "
                        "{%0,%1,%2,%3}, {%4,%5,%6,%7}, {%8,%9}, {%0,%1,%2,%3};"
                        : "+f"(c[0]), "+f"(c[1]), "+f"(c[2]), "+f"(c[3])
                        : "r"(af[mt][0]), "r"(af[mt][1]), "r"(af[mt][2]), "r"(af[mt][3]),
                          "r"(bf[nt][0]), "r"(bf[nt][1]));
                }
        }
    }
#undef COPY_TILE

    // epilogue
#pragma unroll
    for (int mt = 0; mt < 4; mt++) {
#pragma unroll
        for (int nt = 0; nt < 4; nt++) {
            int r0 = bm + wm + mt * 16 + g;
            int c  = bn + wn + nt * 8 + 2 * tid4;
            if (c < N) {
                if (r0 < M)
                    *(float2*)(C + (size_t)r0 * N + c) =
                        make_float2(acc[mt][nt][0], acc[mt][nt][1]);
                if (r0 + 8 < M)
                    *(float2*)(C + (size_t)(r0 + 8) * N + c) =
                        make_float2(acc[mt][nt][2], acc[mt][nt][3]);
            }
        }
    }
}

template<int KT>
__global__ __launch_bounds__(256, 2) void gemm_ca(const float* __restrict__ A,
                                                  const float* __restrict__ B,
                                                  float* __restrict__ C,
                                                  int M, int N) {
    __shared__ float Asm[2 * ASTG];
    __shared__ float Bsm[2 * BSTG];
    gemm_ca_core<KT>(Asm, Bsm, A, B, C, M, N, blockIdx.y * 128, blockIdx.x * 128);
}

// fused pair: first nx x-blocks compute A@B0 -> C0, rest compute A@B1 -> C1
template<int KT>
__global__ __launch_bounds__(256, 2) void gemm_dual_ca(const float* __restrict__ A,
                                                       const float* __restrict__ B0,
                                                       float* __restrict__ C0,
                                                       const float* __restrict__ B1,
                                                       float* __restrict__ C1,
                                                       int M, int N) {
    __shared__ float Asm[2 * ASTG];
    __shared__ float Bsm[2 * BSTG];
    const int nx = N / 128;
    const bool second = (blockIdx.x >= nx);
    const float* B = second ? B1 : B0;
    float*       C = second ? C1 : C0;
    const int bn = (second ? (blockIdx.x - nx) : blockIdx.x) * 128;
    gemm_ca_core<KT>(Asm, Bsm, A, B, C, M, N, blockIdx.y * 128, bn);
}

// ---------------- helpers ----------------
__device__ __forceinline__ float wsum(float v) {
#pragma unroll
    for (int o = 16; o; o >>= 1) v += __shfl_xor_sync(0xffffffffu, v, o);
    return v;
}

// ---------------- GATv2 layer (proven) + tf32-rounded h output ----------------
__global__ __launch_bounds__(128) void gat_k(const float* __restrict__ xs,
                                             const float* __restrict__ xd,
                                             const float* __restrict__ att,
                                             const float* __restrict__ bias,
                                             const float* __restrict__ gamma,
                                             const float* __restrict__ beta,
                                             const int* __restrict__ off,
                                             const int* __restrict__ csrc,
                                             float* __restrict__ out) {
    const int node = blockIdx.x;
    const int w    = threadIdx.x >> 5;
    const int lane = threadIdx.x & 31;

    const float* ah = att + w * CC;
    const float a0 = ah[lane], a1 = ah[lane + 32], a2 = ah[lane + 64];

    const float* dr = xd + (size_t)node * DD + w * CC;
    const float d0 = dr[lane], d1 = dr[lane + 32], d2 = dr[lane + 64];

    const int s = off[node], e = off[node + 1];

    float mx = -3.0e38f, den = 0.f;
    float acc0 = 0.f, acc1 = 0.f, acc2 = 0.f;

    if (s < e) {
        int sr = __ldg(&csrc[s]);
        const float* xr = xs + (size_t)sr * DD + w * CC;
        float p0 = xr[lane], p1 = xr[lane + 32], p2 = xr[lane + 64];

        for (int j = s; j < e; j++) {
            float s0 = p0, s1 = p1, s2 = p2;
            if (j + 1 < e) {
                int srn = __ldg(&csrc[j + 1]);
                const float* xn = xs + (size_t)srn * DD + w * CC;
                p0 = xn[lane]; p1 = xn[lane + 32]; p2 = xn[lane + 64];
            }
            float m0 = s0 + d0; m0 = (m0 > 0.f) ? m0 : 0.2f * m0;
            float m1 = s1 + d1; m1 = (m1 > 0.f) ? m1 : 0.2f * m1;
            float m2 = s2 + d2; m2 = (m2 > 0.f) ? m2 : 0.2f * m2;
            float p = a0 * m0 + a1 * m1 + a2 * m2;
            p = wsum(p);
            float nm = fmaxf(mx, p);
            float so = __expf(mx - nm);
            float wg = __expf(p - nm);
            den  = den  * so + wg;
            acc0 = acc0 * so + wg * s0;
            acc1 = acc1 * so + wg * s1;
            acc2 = acc2 * so + wg * s2;
            mx = nm;
        }
    }

    float inv = 1.f / (den + 1e-16f);
    int c0 = w * CC + lane;
    float v0 = acc0 * inv + bias[c0];
    float v1 = acc1 * inv + bias[c0 + 32];
    float v2 = acc2 * inv + bias[c0 + 64];

    __shared__ float rs[4], rq[4];
    float sm = v0 + v1 + v2;
    float sq = v0 * v0 + v1 * v1 + v2 * v2;
    sm = wsum(sm); sq = wsum(sq);
    if (lane == 0) { rs[w] = sm; rq[w] = sq; }
    __syncthreads();
    float S = rs[0] + rs[1] + rs[2] + rs[3];
    float Q = rq[0] + rq[1] + rq[2] + rq[3];
    float mean = S * (1.0f / DD);
    float var  = Q * (1.0f / DD) - mean * mean;
    float rinv = rsqrtf(var + 1e-5f);

    float* orow = out + (size_t)node * DD;
    float y0 = (v0 - mean) * rinv * gamma[c0]      + beta[c0];
    float y1 = (v1 - mean) * rinv * gamma[c0 + 32] + beta[c0 + 32];
    float y2 = (v2 - mean) * rinv * gamma[c0 + 64] + beta[c0 + 64];
    y0 = (y0 > 0.f) ? y0 : (__expf(y0) - 1.f);
    y1 = (y1 > 0.f) ? y1 : (__expf(y1) - 1.f);
    y2 = (y2 > 0.f) ? y2 : (__expf(y2) - 1.f);
    // h feeds only GEMM A operands -> pre-round to tf32 (numerics identical
    // to converting inside the GEMM)
    orow[c0]      = tf32r(y0);
    orow[c0 + 32] = tf32r(y1);
    orow[c0 + 64] = tf32r(y2);
}

// ---------------- classifier tail: relu(t1+bc1) -> LN(96) -> @Wc2 + bc2
__global__ __launch_bounds__(128) void cls_k(const float* __restrict__ t1,
                                             const float* __restrict__ bc1,
                                             const float* __restrict__ gc,
                                             const float* __restrict__ bec,
                                             const float* __restrict__ Wc2,
                                             const float* __restrict__ bc2,
                                             float* __restrict__ out) {
    const int node = blockIdx.x;
    const int t = threadIdx.x, w = t >> 5, lane = t & 31;
    __shared__ float z[CC];
    __shared__ float w2[CC * NCLS];
    __shared__ float rs[4], rq[4];

    for (int i = t; i < CC * NCLS; i += 128) w2[i] = Wc2[i];

    float v = 0.f;
    if (t < CC) v = fmaxf(t1[(size_t)node * CC + t] + bc1[t], 0.f);

    float sm = wsum(v), sq = wsum(v * v);
    if (lane == 0) { rs[w] = sm; rq[w] = sq; }
    __syncthreads();
    float S = rs[0] + rs[1] + rs[2] + rs[3];
    float Q = rq[0] + rq[1] + rq[2] + rq[3];
    float mean = S * (1.0f / CC);
    float var  = Q * (1.0f / CC) - mean * mean;
    float rinv = rsqrtf(var + 1e-5f);
    if (t < CC) z[t] = (v - mean) * rinv * gc[t] + bec[t];
    __syncthreads();

    if (t < NCLS) {
        float o = bc2[t];
#pragma unroll 8
        for (int k = 0; k < CC; k++) o = fmaf(z[k], w2[k * NCLS + t], o);
        out[(size_t)node * NCLS + t] = o;
    }
}

// ---------------- launch ----------------
extern "C" void kernel_launch(void* const* d_in, const int* in_sizes, int n_in,
                              void* d_out, int out_size) {
    const float* x   = (const float*)d_in[0];
    const int*   ei  = (const int*)d_in[1];
    const float* Wsrc[3] = {(const float*)d_in[2],  (const float*)d_in[8],  (const float*)d_in[14]};
    const float* Wdst[3] = {(const float*)d_in[3],  (const float*)d_in[9],  (const float*)d_in[15]};
    const float* attp[3] = {(const float*)d_in[4],  (const float*)d_in[10], (const float*)d_in[16]};
    const float* bb[3]   = {(const float*)d_in[5],  (const float*)d_in[11], (const float*)d_in[17]};
    const float* gg[3]   = {(const float*)d_in[6],  (const float*)d_in[12], (const float*)d_in[18]};
    const float* be[3]   = {(const float*)d_in[7],  (const float*)d_in[13], (const float*)d_in[19]};
    const float* Wc1 = (const float*)d_in[20];
    const float* bc1 = (const float*)d_in[21];
    const float* gc  = (const float*)d_in[22];
    const float* bec = (const float*)d_in[23];
    const float* Wc2 = (const float*)d_in[24];
    const float* bc2 = (const float*)d_in[25];
    float* out = (float*)d_out;

    float *xs, *xd, *h, *t1, *xc, *wc;
    int *off, *cur, *eid, *csrc;
    cudaGetSymbolAddress((void**)&xs,   g_xs);
    cudaGetSymbolAddress((void**)&xd,   g_xd);
    cudaGetSymbolAddress((void**)&h,    g_h);
    cudaGetSymbolAddress((void**)&t1,   g_t1);
    cudaGetSymbolAddress((void**)&xc,   g_xc);
    cudaGetSymbolAddress((void**)&wc,   g_wc);
    cudaGetSymbolAddress((void**)&off,  g_off);
    cudaGetSymbolAddress((void**)&cur,  g_cur);
    cudaGetSymbolAddress((void**)&eid,  g_eid);
    cudaGetSymbolAddress((void**)&csrc, g_csrc);

    const int* src = ei;
    const int* dst = ei + EE;

    dim3 gd(2 * (DD / 128), (NN + 127) / 128); // 6 x 391

    // CSR build (proven)
    cudaMemsetAsync(cur, 0, NN * sizeof(int));
    hist_k<<<(EE + 255) / 256, 256>>>(dst, cur);
    scan_k<<<1, 1024>>>(cur, off, cur);
    scatter_k<<<(EE + 255) / 256, 256>>>(dst, cur, eid);
    sortsrc_k<<<(NN + 127) / 128, 128>>>(src, off, eid, csrc);

    // tf32 pre-conversion (x + all GEMM weights, original [K][N] layouts)
    cvtx_k<<<(NN * FIN + 255) / 256, 256>>>(x, xc, NN * FIN);
    cvtx_k<<<(30720 + 255) / 256, 256>>>(Wsrc[0], wc + W_S0, 30720);
    cvtx_k<<<(30720 + 255) / 256, 256>>>(Wdst[0], wc + W_D0, 30720);
    cvtx_k<<<(147456 + 255) / 256, 256>>>(Wsrc[1], wc + W_S1, 147456);
    cvtx_k<<<(147456 + 255) / 256, 256>>>(Wdst[1], wc + W_D1, 147456);
    cvtx_k<<<(147456 + 255) / 256, 256>>>(Wsrc[2], wc + W_S2, 147456);
    cvtx_k<<<(147456 + 255) / 256, 256>>>(Wdst[2], wc + W_D2, 147456);
    cvtx_k<<<(36864 + 255) / 256, 256>>>(Wc1, wc + W_C1, 36864);

    // layer 0 (K=80 -> KT=5)
    gemm_dual_ca<5><<<gd, 256>>>(xc, wc + W_S0, xs, wc + W_D0, xd, NN, DD);
    gat_k<<<NN, 128>>>(xs, xd, attp[0], bb[0], gg[0], be[0], off, csrc, h);

    // layers 1..2 (K=384 -> KT=24)
    gemm_dual_ca<24><<<gd, 256>>>(h, wc + W_S1, xs, wc + W_D1, xd, NN, DD);
    gat_k<<<NN, 128>>>(xs, xd, attp[1], bb[1], gg[1], be[1], off, csrc, h);
    gemm_dual_ca<24><<<gd, 256>>>(h, wc + W_S2, xs, wc + W_D2, xd, NN, DD);
    gat_k<<<NN, 128>>>(xs, xd, attp[2], bb[2], gg[2], be[2], off, csrc, h);

    // classifier (N=96, zfill guards handle the partial tile)
    dim3 g2(1, (NN + 127) / 128);
    gemm_ca<24><<<g2, 256>>>(h, wc + W_C1, t1, NN, CC);
    cls_k<<<NN, 128>>>(t1, bc1, gc, bec, Wc2, bc2, out);
}

// round 15
// speedup vs baseline: 1.2335x; 1.0570x over previous
#include <cuda_runtime.h>
#include <cstdint>

#define NN    50000
#define EE    800000
#define FIN   80
#define HH    4
#define CC    96
#define DD    384
#define NCLS  20

// weight offsets in the converted-weights buffer (floats)
#define W_S0  0
#define W_D0  30720
#define W_S1  61440
#define W_D1  208896
#define W_S2  356352
#define W_D2  503808
#define W_C1  651264
#define W_TOT 688128

// ---------------- device scratch (no allocations allowed) ----------------
__device__ float g_xs[(size_t)NN * DD];
__device__ float g_xd[(size_t)NN * DD];
__device__ float g_h [(size_t)NN * DD];
__device__ float g_t1[(size_t)NN * CC];
__device__ float g_xc[(size_t)NN * FIN];   // tf32-rounded x
__device__ float g_wc[W_TOT];              // tf32-rounded weights
__device__ int   g_off[NN + 1];
__device__ int   g_cur[NN];
__device__ int   g_eid[EE];
__device__ int   g_csrc[EE];

__device__ __forceinline__ uint32_t f2tf32(float f) {
    uint32_t r;
    asm("cvt.rna.tf32.f32 %0, %1;" : "=r"(r) : "f"(f));
    return r;
}
__device__ __forceinline__ float tf32r(float f) { return __uint_as_float(f2tf32(f)); }

// ---------------- CSR build (proven) ----------------
__global__ void hist_k(const int* __restrict__ dst, int* __restrict__ cnt) {
    int i = blockIdx.x * blockDim.x + threadIdx.x;
    if (i < EE) atomicAdd(&cnt[dst[i]], 1);
}

// warp-shuffle scan; writes exclusive offsets to off AND cur
__global__ void scan_k(const int* __restrict__ cnt, int* __restrict__ off,
                       int* __restrict__ cur) {
    __shared__ int wsums[32];
    __shared__ int carry_s;
    const int t = threadIdx.x, lane = t & 31, wp = t >> 5;
    if (t == 0) carry_s = 0;
    __syncthreads();
    for (int base = 0; base < NN; base += 1024) {
        int i = base + t;
        int v = (i < NN) ? cnt[i] : 0;
        int x = v;
#pragma unroll
        for (int o = 1; o < 32; o <<= 1) {
            int y = __shfl_up_sync(0xffffffffu, x, o);
            if (lane >= o) x += y;
        }
        if (lane == 31) wsums[wp] = x;
        __syncthreads();
        if (wp == 0) {
            int ws = wsums[lane];
#pragma unroll
            for (int o = 1; o < 32; o <<= 1) {
                int y = __shfl_up_sync(0xffffffffu, ws, o);
                if (lane >= o) ws += y;
            }
            wsums[lane] = ws;
        }
        __syncthreads();
        int add = (wp > 0) ? wsums[wp - 1] : 0;
        int excl = carry_s + x + add - v;
        if (i < NN) { off[i] = excl; cur[i] = excl; }
        int tot = wsums[31];
        __syncthreads();
        if (t == 0) carry_s += tot;
        __syncthreads();
    }
    if (t == 0) off[NN] = carry_s;
}

__global__ void scatter_k(const int* __restrict__ dst, int* __restrict__ cur,
                          int* __restrict__ eid) {
    int i = blockIdx.x * blockDim.x + threadIdx.x;
    if (i < EE) {
        int d = dst[i];
        int p = atomicAdd(&cur[d], 1);
        eid[p] = i;
    }
}

__global__ void sortsrc_k(const int* __restrict__ srcArr, const int* __restrict__ off,
                          int* __restrict__ eid, int* __restrict__ csrc) {
    int v = blockIdx.x * blockDim.x + threadIdx.x;
    if (v >= NN) return;
    int s = off[v], e = off[v + 1];
    for (int i = s + 1; i < e; i++) {
        int key = eid[i];
        int j = i - 1;
        while (j >= s && eid[j] > key) { eid[j + 1] = eid[j]; j--; }
        eid[j + 1] = key;
    }
    for (int i = s; i < e; i++) csrc[i] = srcArr[eid[i]];
}

// ---------------- tf32 pre-conversion ----------------
__global__ void cvtx_k(const float* __restrict__ in, float* __restrict__ outp, int n) {
    int i = blockIdx.x * blockDim.x + threadIdx.x;
    if (i < n) outp[i] = tf32r(in[i]);
}

// ---------------- cp.async tf32 GEMM (R13-proven) ----------------
#define ASTG (128 * 20)
#define BSTG (16 * 136)

template<int KT>
__device__ __forceinline__ void gemm_ca_core(float* Asm, float* Bsm,
                                             const float* __restrict__ A,
                                             const float* __restrict__ B,
                                             float* __restrict__ C,
                                             int M, int N, int bm, int bn) {
    const int K    = KT * 16;
    const int t    = threadIdx.x;
    const int lane = t & 31;
    const int w    = t >> 5;
    const int wm   = (w & 1) * 64;
    const int wn   = (w >> 1) * 32;
    const int g    = lane >> 2;
    const int tid4 = lane & 3;

    float acc[4][4][4];
#pragma unroll
    for (int i = 0; i < 4; i++)
#pragma unroll
        for (int j = 0; j < 4; j++)
#pragma unroll
            for (int r = 0; r < 4; r++) acc[i][j][r] = 0.f;

    const int am  = t >> 2;
    const int ac4 = (t & 3) * 4;
    const int bkr = t >> 5;
    const int bnc = (t & 31) * 4;

    const int gm0 = bm + am, gm1 = bm + am + 64;
    const int asz0 = (gm0 < M) ? 16 : 0;
    const int asz1 = (gm1 < M) ? 16 : 0;
    const float* agp0 = A + (size_t)(asz0 ? gm0 : 0) * K + ac4;
    const float* agp1 = A + (size_t)(asz1 ? gm1 : 0) * K + ac4;

    const int gn  = bn + bnc;
    const int bsz = (gn < N) ? 16 : 0;
    const float* bgp0 = B + (size_t)bkr * N + (bsz ? gn : 0);
    const float* bgp1 = B + (size_t)(bkr + 8) * N + (bsz ? gn : 0);

    const uint32_t sA = (uint32_t)__cvta_generic_to_shared(Asm);
    const uint32_t sB = (uint32_t)__cvta_generic_to_shared(Bsm);
    const uint32_t ad0 = sA + (uint32_t)(am * 20 + ac4) * 4;
    const uint32_t ad1 = sA + (uint32_t)((am + 64) * 20 + ac4) * 4;
    const uint32_t bd0 = sB + (uint32_t)(bkr * 136 + bnc) * 4;
    const uint32_t bd1 = sB + (uint32_t)((bkr + 8) * 136 + bnc) * 4;

#define COPY_TILE(stg, ktt)                                                         \
    do {                                                                            \
        const uint32_t soa = (uint32_t)(stg) * (ASTG * 4);                          \
        const uint32_t sob = (uint32_t)(stg) * (BSTG * 4);                          \
        asm volatile("cp.async.cg.shared.global [%0], [%1], 16, %2;"                \
                     :: "r"(ad0 + soa), "l"(agp0 + (ktt) * 16), "r"(asz0));         \
        asm volatile("cp.async.cg.shared.global [%0], [%1], 16, %2;"                \
                     :: "r"(ad1 + soa), "l"(agp1 + (ktt) * 16), "r"(asz1));         \
        asm volatile("cp.async.cg.shared.global [%0], [%1], 16, %2;"                \
                     :: "r"(bd0 + sob), "l"(bgp0 + (size_t)(ktt) * 16 * N), "r"(bsz)); \
        asm volatile("cp.async.cg.shared.global [%0], [%1], 16, %2;"                \
                     :: "r"(bd1 + sob), "l"(bgp1 + (size_t)(ktt) * 16 * N), "r"(bsz)); \
    } while (0)

    COPY_TILE(0, 0);
    asm volatile("cp.async.commit_group;");

#pragma unroll 2
    for (int kt = 0; kt < KT; kt++) {
        asm volatile("cp.async.wait_group 0;");
        __syncthreads();
        if (kt + 1 < KT) {
            COPY_TILE((kt + 1) & 1, kt + 1);
            asm volatile("cp.async.commit_group;");
        }

        const float* As_ = Asm + (kt & 1) * ASTG;
        const float* Bs_ = Bsm + (kt & 1) * BSTG;
#pragma unroll
        for (int ks = 0; ks < 2; ks++) {
            const int kb = ks * 8;
            uint32_t af[4][4];
#pragma unroll
            for (int mt = 0; mt < 4; mt++) {
                const int m = wm + mt * 16 + g;
                af[mt][0] = __float_as_uint(As_[m * 20 + kb + tid4]);
                af[mt][1] = __float_as_uint(As_[(m + 8) * 20 + kb + tid4]);
                af[mt][2] = __float_as_uint(As_[m * 20 + kb + tid4 + 4]);
                af[mt][3] = __float_as_uint(As_[(m + 8) * 20 + kb + tid4 + 4]);
            }
            uint32_t bf[4][2];
#pragma unroll
            for (int nt = 0; nt < 4; nt++) {
                const int n = wn + nt * 8 + g;
                bf[nt][0] = __float_as_uint(Bs_[(kb + tid4) * 136 + n]);
                bf[nt][1] = __float_as_uint(Bs_[(kb + tid4 + 4) * 136 + n]);
            }
#pragma unroll
            for (int mt = 0; mt < 4; mt++)
#pragma unroll
                for (int nt = 0; nt < 4; nt++) {
                    float* c = acc[mt][nt];
                    asm volatile(
                        "mma.sync.aligned.m16n8k8.row.col.f32.tf32.tf32.f32 "
                        "{%0,%1,%2,%3}, {%4,%5,%6,%7}, {%8,%9}, {%0,%1,%2,%3};"
                        : "+f"(c[0]), "+f"(c[1]), "+f"(c[2]), "+f"(c[3])
                        : "r"(af[mt][0]), "r"(af[mt][1]), "r"(af[mt][2]), "r"(af[mt][3]),
                          "r"(bf[nt][0]), "r"(bf[nt][1]));
                }
        }
    }
#undef COPY_TILE

    // epilogue
#pragma unroll
    for (int mt = 0; mt < 4; mt++) {
#pragma unroll
        for (int nt = 0; nt < 4; nt++) {
            int r0 = bm + wm + mt * 16 + g;
            int c  = bn + wn + nt * 8 + 2 * tid4;
            if (c < N) {
                if (r0 < M)
                    *(float2*)(C + (size_t)r0 * N + c) =
                        make_float2(acc[mt][nt][0], acc[mt][nt][1]);
                if (r0 + 8 < M)
                    *(float2*)(C + (size_t)(r0 + 8) * N + c) =
                        make_float2(acc[mt][nt][2], acc[mt][nt][3]);
            }
        }
    }
}

template<int KT>
__global__ __launch_bounds__(256, 2) void gemm_ca(const float* __restrict__ A,
                                                  const float* __restrict__ B,
                                                  float* __restrict__ C,
                                                  int M, int N) {
    __shared__ float Asm[2 * ASTG];
    __shared__ float Bsm[2 * BSTG];
    gemm_ca_core<KT>(Asm, Bsm, A, B, C, M, N, blockIdx.y * 128, blockIdx.x * 128);
}

template<int KT>
__global__ __launch_bounds__(256, 2) void gemm_dual_ca(const float* __restrict__ A,
                                                       const float* __restrict__ B0,
                                                       float* __restrict__ C0,
                                                       const float* __restrict__ B1,
                                                       float* __restrict__ C1,
                                                       int M, int N) {
    __shared__ float Asm[2 * ASTG];
    __shared__ float Bsm[2 * BSTG];
    const int nx = N / 128;
    const bool second = (blockIdx.x >= nx);
    const float* B = second ? B1 : B0;
    float*       C = second ? C1 : C0;
    const int bn = (second ? (blockIdx.x - nx) : blockIdx.x) * 128;
    gemm_ca_core<KT>(Asm, Bsm, A, B, C, M, N, blockIdx.y * 128, bn);
}

// ---------------- helpers ----------------
__device__ __forceinline__ float wsum(float v) {
#pragma unroll
    for (int o = 16; o; o >>= 1) v += __shfl_xor_sync(0xffffffffu, v, o);
    return v;
}

// ---------------- GATv2 layer: chunk-4 scoring (predication-free main loop)
// one block (128 threads) per node; warp w = head w. Full chunks of 4 edges
// pipeline their 4 independent shuffle-reduction trees; one chunk-max +
// one rescale per chunk. Remainder (<4 edges) uses the proven serial path.
__global__ __launch_bounds__(128) void gat_k(const float* __restrict__ xs,
                                             const float* __restrict__ xd,
                                             const float* __restrict__ att,
                                             const float* __restrict__ bias,
                                             const float* __restrict__ gamma,
                                             const float* __restrict__ beta,
                                             const int* __restrict__ off,
                                             const int* __restrict__ csrc,
                                             float* __restrict__ out) {
    const int node = blockIdx.x;
    const int w    = threadIdx.x >> 5;
    const int lane = threadIdx.x & 31;

    const float* ah = att + w * CC;
    const float a0 = ah[lane], a1 = ah[lane + 32], a2 = ah[lane + 64];

    const float* dr = xd + (size_t)node * DD + w * CC;
    const float d0 = dr[lane], d1 = dr[lane + 32], d2 = dr[lane + 64];

    const int s = off[node], e = off[node + 1];

    float mx = -3.0e38f, den = 0.f;
    float acc0 = 0.f, acc1 = 0.f, acc2 = 0.f;

    const int nfull = s + ((e - s) & ~3);
    int j = s;

    // main loop: full chunks of 4 (no predication)
    for (; j < nfull; j += 4) {
        float sv0[4], sv1[4], sv2[4], sc[4];
#pragma unroll
        for (int u = 0; u < 4; u++) {
            int sr = __ldg(&csrc[j + u]);
            const float* xr = xs + (size_t)sr * DD + w * CC;
            sv0[u] = xr[lane]; sv1[u] = xr[lane + 32]; sv2[u] = xr[lane + 64];
        }
#pragma unroll
        for (int u = 0; u < 4; u++) {
            float m0 = sv0[u] + d0; m0 = (m0 > 0.f) ? m0 : 0.2f * m0;
            float m1 = sv1[u] + d1; m1 = (m1 > 0.f) ? m1 : 0.2f * m1;
            float m2 = sv2[u] + d2; m2 = (m2 > 0.f) ? m2 : 0.2f * m2;
            sc[u] = wsum(a0 * m0 + a1 * m1 + a2 * m2);
        }
        float cm = mx;
#pragma unroll
        for (int u = 0; u < 4; u++) cm = fmaxf(cm, sc[u]);
        float so = __expf(mx - cm);
        den *= so; acc0 *= so; acc1 *= so; acc2 *= so;
#pragma unroll
        for (int u = 0; u < 4; u++) {
            float wg = __expf(sc[u] - cm);
            den  += wg;
            acc0 += wg * sv0[u];
            acc1 += wg * sv1[u];
            acc2 += wg * sv2[u];
        }
        mx = cm;
    }

    // remainder: proven serial online softmax
    for (; j < e; j++) {
        int sr = __ldg(&csrc[j]);
        const float* xr = xs + (size_t)sr * DD + w * CC;
        float s0 = xr[lane], s1 = xr[lane + 32], s2 = xr[lane + 64];
        float m0 = s0 + d0; m0 = (m0 > 0.f) ? m0 : 0.2f * m0;
        float m1 = s1 + d1; m1 = (m1 > 0.f) ? m1 : 0.2f * m1;
        float m2 = s2 + d2; m2 = (m2 > 0.f) ? m2 : 0.2f * m2;
        float p = wsum(a0 * m0 + a1 * m1 + a2 * m2);
        float nm = fmaxf(mx, p);
        float so = __expf(mx - nm);
        float wg = __expf(p - nm);
        den  = den  * so + wg;
        acc0 = acc0 * so + wg * s0;
        acc1 = acc1 * so + wg * s1;
        acc2 = acc2 * so + wg * s2;
        mx = nm;
    }

    float inv = 1.f / (den + 1e-16f);
    int c0 = w * CC + lane;
    float v0 = acc0 * inv + bias[c0];
    float v1 = acc1 * inv + bias[c0 + 32];
    float v2 = acc2 * inv + bias[c0 + 64];

    // block LayerNorm over DD=384, then ELU
    __shared__ float rs[4], rq[4];
    float sm = v0 + v1 + v2;
    float sq = v0 * v0 + v1 * v1 + v2 * v2;
    sm = wsum(sm); sq = wsum(sq);
    if (lane == 0) { rs[w] = sm; rq[w] = sq; }
    __syncthreads();
    float S = rs[0] + rs[1] + rs[2] + rs[3];
    float Q = rq[0] + rq[1] + rq[2] + rq[3];
    float mean = S * (1.0f / DD);
    float var  = Q * (1.0f / DD) - mean * mean;
    float rinv = rsqrtf(var + 1e-5f);

    float* orow = out + (size_t)node * DD;
    float y0 = (v0 - mean) * rinv * gamma[c0]      + beta[c0];
    float y1 = (v1 - mean) * rinv * gamma[c0 + 32] + beta[c0 + 32];
    float y2 = (v2 - mean) * rinv * gamma[c0 + 64] + beta[c0 + 64];
    y0 = (y0 > 0.f) ? y0 : (__expf(y0) - 1.f);
    y1 = (y1 > 0.f) ? y1 : (__expf(y1) - 1.f);
    y2 = (y2 > 0.f) ? y2 : (__expf(y2) - 1.f);
    // h feeds only GEMM A operands -> pre-round to tf32
    orow[c0]      = tf32r(y0);
    orow[c0 + 32] = tf32r(y1);
    orow[c0 + 64] = tf32r(y2);
}

// ---------------- classifier tail: relu(t1+bc1) -> LN(96) -> @Wc2 + bc2
__global__ __launch_bounds__(128) void cls_k(const float* __restrict__ t1,
                                             const float* __restrict__ bc1,
                                             const float* __restrict__ gc,
                                             const float* __restrict__ bec,
                                             const float* __restrict__ Wc2,
                                             const float* __restrict__ bc2,
                                             float* __restrict__ out) {
    const int node = blockIdx.x;
    const int t = threadIdx.x, w = t >> 5, lane = t & 31;
    __shared__ float z[CC];
    __shared__ float w2[CC * NCLS];
    __shared__ float rs[4], rq[4];

    for (int i = t; i < CC * NCLS; i += 128) w2[i] = Wc2[i];

    float v = 0.f;
    if (t < CC) v = fmaxf(t1[(size_t)node * CC + t] + bc1[t], 0.f);

    float sm = wsum(v), sq = wsum(v * v);
    if (lane == 0) { rs[w] = sm; rq[w] = sq; }
    __syncthreads();
    float S = rs[0] + rs[1] + rs[2] + rs[3];
    float Q = rq[0] + rq[1] + rq[2] + rq[3];
    float mean = S * (1.0f / CC);
    float var  = Q * (1.0f / CC) - mean * mean;
    float rinv = rsqrtf(var + 1e-5f);
    if (t < CC) z[t] = (v - mean) * rinv * gc[t] + bec[t];
    __syncthreads();

    if (t < NCLS) {
        float o = bc2[t];
#pragma unroll 8
        for (int k = 0; k < CC; k++) o = fmaf(z[k], w2[k * NCLS + t], o);
        out[(size_t)node * NCLS + t] = o;
    }
}

// ---------------- launch ----------------
extern "C" void kernel_launch(void* const* d_in, const int* in_sizes, int n_in,
                              void* d_out, int out_size) {
    const float* x   = (const float*)d_in[0];
    const int*   ei  = (const int*)d_in[1];
    const float* Wsrc[3] = {(const float*)d_in[2],  (const float*)d_in[8],  (const float*)d_in[14]};
    const float* Wdst[3] = {(const float*)d_in[3],  (const float*)d_in[9],  (const float*)d_in[15]};
    const float* attp[3] = {(const float*)d_in[4],  (const float*)d_in[10], (const float*)d_in[16]};
    const float* bb[3]   = {(const float*)d_in[5],  (const float*)d_in[11], (const float*)d_in[17]};
    const float* gg[3]   = {(const float*)d_in[6],  (const float*)d_in[12], (const float*)d_in[18]};
    const float* be[3]   = {(const float*)d_in[7],  (const float*)d_in[13], (const float*)d_in[19]};
    const float* Wc1 = (const float*)d_in[20];
    const float* bc1 = (const float*)d_in[21];
    const float* gc  = (const float*)d_in[22];
    const float* bec = (const float*)d_in[23];
    const float* Wc2 = (const float*)d_in[24];
    const float* bc2 = (const float*)d_in[25];
    float* out = (float*)d_out;

    float *xs, *xd, *h, *t1, *xc, *wc;
    int *off, *cur, *eid, *csrc;
    cudaGetSymbolAddress((void**)&xs,   g_xs);
    cudaGetSymbolAddress((void**)&xd,   g_xd);
    cudaGetSymbolAddress((void**)&h,    g_h);
    cudaGetSymbolAddress((void**)&t1,   g_t1);
    cudaGetSymbolAddress((void**)&xc,   g_xc);
    cudaGetSymbolAddress((void**)&wc,   g_wc);
    cudaGetSymbolAddress((void**)&off,  g_off);
    cudaGetSymbolAddress((void**)&cur,  g_cur);
    cudaGetSymbolAddress((void**)&eid,  g_eid);
    cudaGetSymbolAddress((void**)&csrc, g_csrc);

    const int* src = ei;
    const int* dst = ei + EE;

    dim3 gd(2 * (DD / 128), (NN + 127) / 128); // 6 x 391

    // CSR build (proven)
    cudaMemsetAsync(cur, 0, NN * sizeof(int));
    hist_k<<<(EE + 255) / 256, 256>>>(dst, cur);
    scan_k<<<1, 1024>>>(cur, off, cur);
    scatter_k<<<(EE + 255) / 256, 256>>>(dst, cur, eid);
    sortsrc_k<<<(NN + 127) / 128, 128>>>(src, off, eid, csrc);

    // tf32 pre-conversion (x + all GEMM weights)
    cvtx_k<<<(NN * FIN + 255) / 256, 256>>>(x, xc, NN * FIN);
    cvtx_k<<<(30720 + 255) / 256, 256>>>(Wsrc[0], wc + W_S0, 30720);
    cvtx_k<<<(30720 + 255) / 256, 256>>>(Wdst[0], wc + W_D0, 30720);
    cvtx_k<<<(147456 + 255) / 256, 256>>>(Wsrc[1], wc + W_S1, 147456);
    cvtx_k<<<(147456 + 255) / 256, 256>>>(Wdst[1], wc + W_D1, 147456);
    cvtx_k<<<(147456 + 255) / 256, 256>>>(Wsrc[2], wc + W_S2, 147456);
    cvtx_k<<<(147456 + 255) / 256, 256>>>(Wdst[2], wc + W_D2, 147456);
    cvtx_k<<<(36864 + 255) / 256, 256>>>(Wc1, wc + W_C1, 36864);

    // layer 0 (K=80 -> KT=5)
    gemm_dual_ca<5><<<gd, 256>>>(xc, wc + W_S0, xs, wc + W_D0, xd, NN, DD);
    gat_k<<<NN, 128>>>(xs, xd, attp[0], bb[0], gg[0], be[0], off, csrc, h);

    // layers 1..2 (K=384 -> KT=24)
    gemm_dual_ca<24><<<gd, 256>>>(h, wc + W_S1, xs, wc + W_D1, xd, NN, DD);
    gat_k<<<NN, 128>>>(xs, xd, attp[1], bb[1], gg[1], be[1], off, csrc, h);
    gemm_dual_ca<24><<<gd, 256>>>(h, wc + W_S2, xs, wc + W_D2, xd, NN, DD);
    gat_k<<<NN, 128>>>(xs, xd, attp[2], bb[2], gg[2], be[2], off, csrc, h);

    // classifier (N=96, zfill guards handle the partial tile)
    dim3 g2(1, (NN + 127) / 128);
    gemm_ca<24><<<g2, 256>>>(h, wc + W_C1, t1, NN, CC);
    cls_k<<<NN, 128>>>(t1, bc1, gc, bec, Wc2, bc2, out);
}

// round 17
// speedup vs baseline: 1.3436x; 1.0893x over previous
#include <cuda_runtime.h>
#include <cuda_fp16.h>
#include <cstdint>

#define NN    50000
#define EE    800000
#define FIN   80
#define HH    4
#define CC    96
#define DD    384
#define NCLS  20

// transposed-weight offsets (halves), layout [N][K]
#define W_S0  0         // [384][80]
#define W_D0  30720
#define W_S1  61440     // [384][384]
#define W_D1  208896
#define W_S2  356352
#define W_D2  503808
#define W_C1  651264    // [96][384]
#define W_TOT 688128

// ---------------- device scratch (no allocations allowed) ----------------
__device__ float  g_xs[(size_t)NN * DD];
__device__ float  g_xd[(size_t)NN * DD];
__device__ __half g_hh[(size_t)NN * DD];    // gat output as fp16 (GEMM A)
__device__ float  g_t1[(size_t)NN * CC];
__device__ __half g_xh[(size_t)NN * FIN];   // fp16 x
__device__ __half g_wh[W_TOT];              // fp16 transposed weights
__device__ int    g_off[NN + 1];
__device__ int    g_cur[NN];
__device__ int    g_eid[EE];
__device__ int    g_csrc[EE];

// ---------------- CSR build (proven) ----------------
__global__ void hist_k(const int* __restrict__ dst, int* __restrict__ cnt) {
    int i = blockIdx.x * blockDim.x + threadIdx.x;
    if (i < EE) atomicAdd(&cnt[dst[i]], 1);
}

__global__ void scan_k(const int* __restrict__ cnt, int* __restrict__ off,
                       int* __restrict__ cur) {
    __shared__ int wsums[32];
    __shared__ int carry_s;
    const int t = threadIdx.x, lane = t & 31, wp = t >> 5;
    if (t == 0) carry_s = 0;
    __syncthreads();
    for (int base = 0; base < NN; base += 1024) {
        int i = base + t;
        int v = (i < NN) ? cnt[i] : 0;
        int x = v;
#pragma unroll
        for (int o = 1; o < 32; o <<= 1) {
            int y = __shfl_up_sync(0xffffffffu, x, o);
            if (lane >= o) x += y;
        }
        if (lane == 31) wsums[wp] = x;
        __syncthreads();
        if (wp == 0) {
            int ws = wsums[lane];
#pragma unroll
            for (int o = 1; o < 32; o <<= 1) {
                int y = __shfl_up_sync(0xffffffffu, ws, o);
                if (lane >= o) ws += y;
            }
            wsums[lane] = ws;
        }
        __syncthreads();
        int add = (wp > 0) ? wsums[wp - 1] : 0;
        int excl = carry_s + x + add - v;
        if (i < NN) { off[i] = excl; cur[i] = excl; }
        int tot = wsums[31];
        __syncthreads();
        if (t == 0) carry_s += tot;
        __syncthreads();
    }
    if (t == 0) off[NN] = carry_s;
}

__global__ void scatter_k(const int* __restrict__ dst, int* __restrict__ cur,
                          int* __restrict__ eid) {
    int i = blockIdx.x * blockDim.x + threadIdx.x;
    if (i < EE) {
        int d = dst[i];
        int p = atomicAdd(&cur[d], 1);
        eid[p] = i;
    }
}

__global__ void sortsrc_k(const int* __restrict__ srcArr, const int* __restrict__ off,
                          int* __restrict__ eid, int* __restrict__ csrc) {
    int v = blockIdx.x * blockDim.x + threadIdx.x;
    if (v >= NN) return;
    int s = off[v], e = off[v + 1];
    for (int i = s + 1; i < e; i++) {
        int key = eid[i];
        int j = i - 1;
        while (j >= s && eid[j] > key) { eid[j + 1] = eid[j]; j--; }
        eid[j + 1] = key;
    }
    for (int i = s; i < e; i++) csrc[i] = srcArr[eid[i]];
}

// ---------------- fp16 conversions ----------------
__global__ void cvth_k(const float* __restrict__ in, __half* __restrict__ outp, int n) {
    int i = blockIdx.x * blockDim.x + threadIdx.x;
    if (i < n) outp[i] = __float2half(in[i]);
}
// W [K][N] fp32 -> [N][K] fp16
__global__ void cvtTh_k(const float* __restrict__ in, __half* __restrict__ outp,
                        int K, int N) {
    int i = blockIdx.x * blockDim.x + threadIdx.x;
    if (i < K * N) {
        int n = i / K, k = i % K;
        outp[i] = __float2half(in[(size_t)k * N + n]);
    }
}

// ---------------- fp16 tensor GEMM: C[M,N] = A[M,K] @ BT[N,K]^T ----------------
// 128x128 CTA tile, 8 warps (64x32 each), BK=16, mma.m16n8k16.f16 (fp32 accum).
// Single-barrier cp.async pipeline (R13-proven structure).
// SMEM rows stride 12 words (8 data + 4 pad): conflict-free fragment LDS.
#define HSTG (128 * 12)   // words per stage (A or B)

template<int KT>
__device__ __forceinline__ void gemm_h_core(uint32_t* Asm, uint32_t* Bsm,
                                            const __half* __restrict__ A,
                                            const __half* __restrict__ BT,
                                            float* __restrict__ C,
                                            int M, int N, int bm, int bn) {
    const int K    = KT * 16;
    const int t    = threadIdx.x;
    const int lane = t & 31;
    const int w    = t >> 5;
    const int wm   = (w & 1) * 64;
    const int wn   = (w >> 1) * 32;
    const int g    = lane >> 2;
    const int tid4 = lane & 3;

    float acc[4][4][4];
#pragma unroll
    for (int i = 0; i < 4; i++)
#pragma unroll
        for (int j = 0; j < 4; j++)
#pragma unroll
            for (int r = 0; r < 4; r++) acc[i][j][r] = 0.f;

    // copy mapping: 256 threads, each 1 A-chunk + 1 B-chunk (16B = 8 halves)
    const int row = t >> 1;          // 0..127
    const int ch  = t & 1;           // chunk within row

    const int gm  = bm + row;
    const int asz = (gm < M) ? 16 : 0;
    const __half* agp = A + (size_t)(asz ? gm : 0) * K + ch * 8;

    const int gnr = bn + row;
    const int bsz = (gnr < N) ? 16 : 0;
    const __half* bgp = BT + (size_t)(bsz ? gnr : 0) * K + ch * 8;

    const uint32_t sA = (uint32_t)__cvta_generic_to_shared(Asm);
    const uint32_t sB = (uint32_t)__cvta_generic_to_shared(Bsm);
    const uint32_t ad = sA + (uint32_t)(row * 12 + ch * 4) * 4;
    const uint32_t bd = sB + (uint32_t)(row * 12 + ch * 4) * 4;

#define COPY_TILE(stg, ktt)                                                      \
    do {                                                                         \
        const uint32_t so = (uint32_t)(stg) * (HSTG * 4);                        \
        asm volatile("cp.async.cg.shared.global [%0], [%1], 16, %2;"             \
                     :: "r"(ad + so), "l"(agp + (ktt) * 16), "r"(asz));          \
        asm volatile("cp.async.cg.shared.global [%0], [%1], 16, %2;"             \
                     :: "r"(bd + so), "l"(bgp + (ktt) * 16), "r"(bsz));          \
    } while (0)

    COPY_TILE(0, 0);
    asm volatile("cp.async.commit_group;");

#pragma unroll 2
    for (int kt = 0; kt < KT; kt++) {
        asm volatile("cp.async.wait_group 0;");
        __syncthreads();
        if (kt + 1 < KT) {
            COPY_TILE((kt + 1) & 1, kt + 1);
            asm volatile("cp.async.commit_group;");
        }

        const uint32_t* As_ = Asm + (kt & 1) * HSTG;
        const uint32_t* Bs_ = Bsm + (kt & 1) * HSTG;

        uint32_t af[4][4];
#pragma unroll
        for (int mt = 0; mt < 4; mt++) {
            const int m = wm + mt * 16 + g;
            af[mt][0] = As_[m * 12 + tid4];
            af[mt][1] = As_[(m + 8) * 12 + tid4];
            af[mt][2] = As_[m * 12 + tid4 + 4];
            af[mt][3] = As_[(m + 8) * 12 + tid4 + 4];
        }
        uint32_t bf[4][2];
#pragma unroll
        for (int nt = 0; nt < 4; nt++) {
            const int n = wn + nt * 8 + g;
            bf[nt][0] = Bs_[n * 12 + tid4];
            bf[nt][1] = Bs_[n * 12 + tid4 + 4];
        }
#pragma unroll
        for (int mt = 0; mt < 4; mt++)
#pragma unroll
            for (int nt = 0; nt < 4; nt++) {
                float* c = acc[mt][nt];
                asm volatile(
                    "mma.sync.aligned.m16n8k16.row.col.f32.f16.f16.f32 "
                    "{%0,%1,%2,%3}, {%4,%5,%6,%7}, {%8,%9}, {%0,%1,%2,%3};"
                    : "+f"(c[0]), "+f"(c[1]), "+f"(c[2]), "+f"(c[3])
                    : "r"(af[mt][0]), "r"(af[mt][1]), "r"(af[mt][2]), "r"(af[mt][3]),
                      "r"(bf[nt][0]), "r"(bf[nt][1]));
            }
    }
#undef COPY_TILE

    // epilogue (C fragment layout identical to tf32 path)
#pragma unroll
    for (int mt = 0; mt < 4; mt++) {
#pragma unroll
        for (int nt = 0; nt < 4; nt++) {
            int r0 = bm + wm + mt * 16 + g;
            int c  = bn + wn + nt * 8 + 2 * tid4;
            if (c < N) {
                if (r0 < M)
                    *(float2*)(C + (size_t)r0 * N + c) =
                        make_float2(acc[mt][nt][0], acc[mt][nt][1]);
                if (r0 + 8 < M)
                    *(float2*)(C + (size_t)(r0 + 8) * N + c) =
                        make_float2(acc[mt][nt][2], acc[mt][nt][3]);
            }
        }
    }
}

template<int KT>
__global__ __launch_bounds__(256, 2) void gemm_h(const __half* __restrict__ A,
                                                 const __half* __restrict__ BT,
                                                 float* __restrict__ C,
                                                 int M, int N) {
    __shared__ uint32_t Asm[2 * HSTG];
    __shared__ uint32_t Bsm[2 * HSTG];
    gemm_h_core<KT>(Asm, Bsm, A, BT, C, M, N, blockIdx.y * 128, blockIdx.x * 128);
}

// fused pair: first nx x-blocks A@B0T'->C0, rest A@B1T'->C1
template<int KT>
__global__ __launch_bounds__(256, 2) void gemm_dual_h(const __half* __restrict__ A,
                                                      const __half* __restrict__ B0T,
                                                      float* __restrict__ C0,
                                                      const __half* __restrict__ B1T,
                                                      float* __restrict__ C1,
                                                      int M, int N) {
    __shared__ uint32_t Asm[2 * HSTG];
    __shared__ uint32_t Bsm[2 * HSTG];
    const int nx = N / 128;
    const bool second = (blockIdx.x >= nx);
    const __half* BT = second ? B1T : B0T;
    float*        C  = second ? C1 : C0;
    const int bn = (second ? (blockIdx.x - nx) : blockIdx.x) * 128;
    gemm_h_core<KT>(Asm, Bsm, A, BT, C, M, N, blockIdx.y * 128, bn);
}

// ---------------- helpers ----------------
__device__ __forceinline__ float wsum(float v) {
#pragma unroll
    for (int o = 16; o; o >>= 1) v += __shfl_xor_sync(0xffffffffu, v, o);
    return v;
}

// ---------------- GATv2 layer (R15-proven chunk-4) + fp16 h output ----------------
__global__ __launch_bounds__(128) void gat_k(const float* __restrict__ xs,
                                             const float* __restrict__ xd,
                                             const float* __restrict__ att,
                                             const float* __restrict__ bias,
                                             const float* __restrict__ gamma,
                                             const float* __restrict__ beta,
                                             const int* __restrict__ off,
                                             const int* __restrict__ csrc,
                                             __half* __restrict__ out) {
    const int node = blockIdx.x;
    const int w    = threadIdx.x >> 5;
    const int lane = threadIdx.x & 31;

    const float* ah = att + w * CC;
    const float a0 = ah[lane], a1 = ah[lane + 32], a2 = ah[lane + 64];

    const float* dr = xd + (size_t)node * DD + w * CC;
    const float d0 = dr[lane], d1 = dr[lane + 32], d2 = dr[lane + 64];

    const int s = off[node], e = off[node + 1];

    float mx = -3.0e38f, den = 0.f;
    float acc0 = 0.f, acc1 = 0.f, acc2 = 0.f;

    const int nfull = s + ((e - s) & ~3);
    int j = s;

    for (; j < nfull; j += 4) {
        float sv0[4], sv1[4], sv2[4], sc[4];
#pragma unroll
        for (int u = 0; u < 4; u++) {
            int sr = __ldg(&csrc[j + u]);
            const float* xr = xs + (size_t)sr * DD + w * CC;
            sv0[u] = xr[lane]; sv1[u] = xr[lane + 32]; sv2[u] = xr[lane + 64];
        }
#pragma unroll
        for (int u = 0; u < 4; u++) {
            float m0 = sv0[u] + d0; m0 = (m0 > 0.f) ? m0 : 0.2f * m0;
            float m1 = sv1[u] + d1; m1 = (m1 > 0.f) ? m1 : 0.2f * m1;
            float m2 = sv2[u] + d2; m2 = (m2 > 0.f) ? m2 : 0.2f * m2;
            sc[u] = wsum(a0 * m0 + a1 * m1 + a2 * m2);
        }
        float cm = mx;
#pragma unroll
        for (int u = 0; u < 4; u++) cm = fmaxf(cm, sc[u]);
        float so = __expf(mx - cm);
        den *= so; acc0 *= so; acc1 *= so; acc2 *= so;
#pragma unroll
        for (int u = 0; u < 4; u++) {
            float wg = __expf(sc[u] - cm);
            den  += wg;
            acc0 += wg * sv0[u];
            acc1 += wg * sv1[u];
            acc2 += wg * sv2[u];
        }
        mx = cm;
    }

    for (; j < e; j++) {
        int sr = __ldg(&csrc[j]);
        const float* xr = xs + (size_t)sr * DD + w * CC;
        float s0 = xr[lane], s1 = xr[lane + 32], s2 = xr[lane + 64];
        float m0 = s0 + d0; m0 = (m0 > 0.f) ? m0 : 0.2f * m0;
        float m1 = s1 + d1; m1 = (m1 > 0.f) ? m1 : 0.2f * m1;
        float m2 = s2 + d2; m2 = (m2 > 0.f) ? m2 : 0.2f * m2;
        float p = wsum(a0 * m0 + a1 * m1 + a2 * m2);
        float nm = fmaxf(mx, p);
        float so = __expf(mx - nm);
        float wg = __expf(p - nm);
        den  = den  * so + wg;
        acc0 = acc0 * so + wg * s0;
        acc1 = acc1 * so + wg * s1;
        acc2 = acc2 * so + wg * s2;
        mx = nm;
    }

    float inv = 1.f / (den + 1e-16f);
    int c0 = w * CC + lane;
    float v0 = acc0 * inv + bias[c0];
    float v1 = acc1 * inv + bias[c0 + 32];
    float v2 = acc2 * inv + bias[c0 + 64];

    __shared__ float rs[4], rq[4];
    float sm = v0 + v1 + v2;
    float sq = v0 * v0 + v1 * v1 + v2 * v2;
    sm = wsum(sm); sq = wsum(sq);
    if (lane == 0) { rs[w] = sm; rq[w] = sq; }
    __syncthreads();
    float S = rs[0] + rs[1] + rs[2] + rs[3];
    float Q = rq[0] + rq[1] + rq[2] + rq[3];
    float mean = S * (1.0f / DD);
    float var  = Q * (1.0f / DD) - mean * mean;
    float rinv = rsqrtf(var + 1e-5f);

    __half* orow = out + (size_t)node * DD;
    float y0 = (v0 - mean) * rinv * gamma[c0]      + beta[c0];
    float y1 = (v1 - mean) * rinv * gamma[c0 + 32] + beta[c0 + 32];
    float y2 = (v2 - mean) * rinv * gamma[c0 + 64] + beta[c0 + 64];
    y0 = (y0 > 0.f) ? y0 : (__expf(y0) - 1.f);
    y1 = (y1 > 0.f) ? y1 : (__expf(y1) - 1.f);
    y2 = (y2 > 0.f) ? y2 : (__expf(y2) - 1.f);
    // h feeds only GEMM A operands -> store fp16 directly
    orow[c0]      = __float2half(y0);
    orow[c0 + 32] = __float2half(y1);
    orow[c0 + 64] = __float2half(y2);
}

// ---------------- classifier tail: relu(t1+bc1) -> LN(96) -> @Wc2 + bc2
__global__ __launch_bounds__(128) void cls_k(const float* __restrict__ t1,
                                             const float* __restrict__ bc1,
                                             const float* __restrict__ gc,
                                             const float* __restrict__ bec,
                                             const float* __restrict__ Wc2,
                                             const float* __restrict__ bc2,
                                             float* __restrict__ out) {
    const int node = blockIdx.x;
    const int t = threadIdx.x, w = t >> 5, lane = t & 31;
    __shared__ float z[CC];
    __shared__ float w2[CC * NCLS];
    __shared__ float rs[4], rq[4];

    for (int i = t; i < CC * NCLS; i += 128) w2[i] = Wc2[i];

    float v = 0.f;
    if (t < CC) v = fmaxf(t1[(size_t)node * CC + t] + bc1[t], 0.f);

    float sm = wsum(v), sq = wsum(v * v);
    if (lane == 0) { rs[w] = sm; rq[w] = sq; }
    __syncthreads();
    float S = rs[0] + rs[1] + rs[2] + rs[3];
    float Q = rq[0] + rq[1] + rq[2] + rq[3];
    float mean = S * (1.0f / CC);
    float var  = Q * (1.0f / CC) - mean * mean;
    float rinv = rsqrtf(var + 1e-5f);
    if (t < CC) z[t] = (v - mean) * rinv * gc[t] + bec[t];
    __syncthreads();

    if (t < NCLS) {
        float o = bc2[t];
#pragma unroll 8
        for (int k = 0; k < CC; k++) o = fmaf(z[k], w2[k * NCLS + t], o);
        out[(size_t)node * NCLS + t] = o;
    }
}

// ---------------- launch ----------------
extern "C" void kernel_launch(void* const* d_in, const int* in_sizes, int n_in,
                              void* d_out, int out_size) {
    const float* x   = (const float*)d_in[0];
    const int*   ei  = (const int*)d_in[1];
    const float* Wsrc[3] = {(const float*)d_in[2],  (const float*)d_in[8],  (const float*)d_in[14]};
    const float* Wdst[3] = {(const float*)d_in[3],  (const float*)d_in[9],  (const float*)d_in[15]};
    const float* attp[3] = {(const float*)d_in[4],  (const float*)d_in[10], (const float*)d_in[16]};
    const float* bb[3]   = {(const float*)d_in[5],  (const float*)d_in[11], (const float*)d_in[17]};
    const float* gg[3]   = {(const float*)d_in[6],  (const float*)d_in[12], (const float*)d_in[18]};
    const float* be[3]   = {(const float*)d_in[7],  (const float*)d_in[13], (const float*)d_in[19]};
    const float* Wc1 = (const float*)d_in[20];
    const float* bc1 = (const float*)d_in[21];
    const float* gc  = (const float*)d_in[22];
    const float* bec = (const float*)d_in[23];
    const float* Wc2 = (const float*)d_in[24];
    const float* bc2 = (const float*)d_in[25];
    float* out = (float*)d_out;

    float *xs, *xd, *t1;
    __half *hh, *xh, *wh;
    int *off, *cur, *eid, *csrc;
    cudaGetSymbolAddress((void**)&xs,   g_xs);
    cudaGetSymbolAddress((void**)&xd,   g_xd);
    cudaGetSymbolAddress((void**)&hh,   g_hh);
    cudaGetSymbolAddress((void**)&t1,   g_t1);
    cudaGetSymbolAddress((void**)&xh,   g_xh);
    cudaGetSymbolAddress((void**)&wh,   g_wh);
    cudaGetSymbolAddress((void**)&off,  g_off);
    cudaGetSymbolAddress((void**)&cur,  g_cur);
    cudaGetSymbolAddress((void**)&eid,  g_eid);
    cudaGetSymbolAddress((void**)&csrc, g_csrc);

    const int* src = ei;
    const int* dst = ei + EE;

    dim3 gd(2 * (DD / 128), (NN + 127) / 128); // 6 x 391

    // CSR build (proven)
    cudaMemsetAsync(cur, 0, NN * sizeof(int));
    hist_k<<<(EE + 255) / 256, 256>>>(dst, cur);
    scan_k<<<1, 1024>>>(cur, off, cur);
    scatter_k<<<(EE + 255) / 256, 256>>>(dst, cur, eid);
    sortsrc_k<<<(NN + 127) / 128, 128>>>(src, off, eid, csrc);

    // fp16 conversions (x flat; weights transposed to [N][K])
    cvth_k<<<(NN * FIN + 255) / 256, 256>>>(x, xh, NN * FIN);
    cvtTh_k<<<(30720 + 255) / 256, 256>>>(Wsrc[0], wh + W_S0, FIN, DD);
    cvtTh_k<<<(30720 + 255) / 256, 256>>>(Wdst[0], wh + W_D0, FIN, DD);
    cvtTh_k<<<(147456 + 255) / 256, 256>>>(Wsrc[1], wh + W_S1, DD, DD);
    cvtTh_k<<<(147456 + 255) / 256, 256>>>(Wdst[1], wh + W_D1, DD, DD);
    cvtTh_k<<<(147456 + 255) / 256, 256>>>(Wsrc[2], wh + W_S2, DD, DD);
    cvtTh_k<<<(147456 + 255) / 256, 256>>>(Wdst[2], wh + W_D2, DD, DD);
    cvtTh_k<<<(36864 + 255) / 256, 256>>>(Wc1, wh + W_C1, DD, CC);

    // layer 0 (K=80 -> KT=5)
    gemm_dual_h<5><<<gd, 256>>>(xh, wh + W_S0, xs, wh + W_D0, xd, NN, DD);
    gat_k<<<NN, 128>>>(xs, xd, attp[0], bb[0], gg[0], be[0], off, csrc, hh);

    // layers 1..2 (K=384 -> KT=24)
    gemm_dual_h<24><<<gd, 256>>>(hh, wh + W_S1, xs, wh + W_D1, xd, NN, DD);
    gat_k<<<NN, 128>>>(xs, xd, attp[1], bb[1], gg[1], be[1], off, csrc, hh);
    gemm_dual_h<24><<<gd, 256>>>(hh, wh + W_S2, xs, wh + W_D2, xd, NN, DD);
    gat_k<<<NN, 128>>>(xs, xd, attp[2], bb[2], gg[2], be[2], off, csrc, hh);

    // classifier (N=96; row guards zero-fill the partial tile)
    dim3 g2(1, (NN + 127) / 128);
    gemm_h<24><<<g2, 256>>>(hh, wh + W_C1, t1, NN, CC);
    cls_k<<<NN, 128>>>(t1, bc1, gc, bec, Wc2, bc2, out);
}